// round 1
// baseline (speedup 1.0000x reference)
#include <cuda_runtime.h>
#include <cstdint>

// Problem constants
#define BB 2
#define SS 1024
#define HH 4096
#define NH 32
#define GG 2
#define HD 128
#define NQKV 4608            // NH*HD + 2*G*HD
#define MROWS (BB*SS)        // 2048

// ---------------- scratch (static device globals; no allocs allowed) ----------
__device__ float g_qkv[MROWS * NQKV];          // [2048, 4608]
__device__ float g_q  [BB * NH * SS * HD];     // [B,NH,S,HD]
__device__ float g_k  [BB * GG * SS * HD];     // [B,G,S,HD]
__device__ float g_v  [BB * GG * SS * HD];     // [B,G,S,HD]
__device__ float g_ctx[MROWS * HH];            // [2048, 4096]

// =============================================================================
// SGEMM: C[M,N] = A[M,K] @ B[K,N] (+ bias[N]); row-major; M,N multiples of 128,
// K multiple of 8. 128x128 tile, BK=8, 256 threads, 8x8 frags (split 4+4).
// =============================================================================
__global__ void __launch_bounds__(256) sgemm_kernel(
    const float* __restrict__ A, const float* __restrict__ B,
    const float* __restrict__ bias, float* __restrict__ C,
    int M, int N, int K)
{
    __shared__ float As[8][128];   // transposed: As[k][m]
    __shared__ float Bs[8][128];   // Bs[k][n]

    const int tid = threadIdx.x;
    const int tx = tid & 15;
    const int ty = tid >> 4;
    const int bm = blockIdx.y * 128;
    const int bn = blockIdx.x * 128;

    // A tile loader: 128 rows x 8 cols -> each thread one float4
    const int ar = tid >> 1;
    const int ac = (tid & 1) * 4;
    // B tile loader: 8 rows x 128 cols -> each thread one float4
    const int brow = tid >> 5;
    const int bcol = (tid & 31) * 4;

    const float* Aptr = A + (size_t)(bm + ar) * K + ac;
    const float* Bptr = B + (size_t)brow * N + bn + bcol;

    float acc[8][8];
#pragma unroll
    for (int i = 0; i < 8; i++)
#pragma unroll
        for (int j = 0; j < 8; j++) acc[i][j] = 0.0f;

    for (int kt = 0; kt < K; kt += 8) {
        float4 a = *(const float4*)(Aptr + kt);
        float4 b = *(const float4*)(Bptr + (size_t)kt * N);
        As[ac + 0][ar] = a.x;
        As[ac + 1][ar] = a.y;
        As[ac + 2][ar] = a.z;
        As[ac + 3][ar] = a.w;
        *(float4*)(&Bs[brow][bcol]) = b;
        __syncthreads();

        float ra[8], rb[8];
#pragma unroll
        for (int k = 0; k < 8; k++) {
            *(float4*)&ra[0] = *(const float4*)&As[k][ty * 4];
            *(float4*)&ra[4] = *(const float4*)&As[k][64 + ty * 4];
            *(float4*)&rb[0] = *(const float4*)&Bs[k][tx * 4];
            *(float4*)&rb[4] = *(const float4*)&Bs[k][64 + tx * 4];
#pragma unroll
            for (int i = 0; i < 8; i++)
#pragma unroll
                for (int j = 0; j < 8; j++)
                    acc[i][j] += ra[i] * rb[j];
        }
        __syncthreads();
    }

    // epilogue
#pragma unroll
    for (int ih = 0; ih < 2; ih++) {
#pragma unroll
        for (int i = 0; i < 4; i++) {
            int r = bm + ih * 64 + ty * 4 + i;
#pragma unroll
            for (int jh = 0; jh < 2; jh++) {
                int c = bn + jh * 64 + tx * 4;
                float4 v;
                v.x = acc[ih * 4 + i][jh * 4 + 0];
                v.y = acc[ih * 4 + i][jh * 4 + 1];
                v.z = acc[ih * 4 + i][jh * 4 + 2];
                v.w = acc[ih * 4 + i][jh * 4 + 3];
                if (bias) {
                    v.x += bias[c + 0];
                    v.y += bias[c + 1];
                    v.z += bias[c + 2];
                    v.w += bias[c + 3];
                }
                *(float4*)(C + (size_t)r * N + c) = v;
            }
        }
    }
}

// =============================================================================
// RoPE + scatter: qkv[2048,4608] -> Q[B,NH,S,HD], K[B,G,S,HD], V[B,G,S,HD]
// One thread per (dim-pair). RoPE on first 64 dims of q and k.
// rope_cache layout: [S, B, 32, 2]
// =============================================================================
__global__ void __launch_bounds__(256) rope_scatter_kernel(
    const float* __restrict__ qkv, const float* __restrict__ rope,
    float* __restrict__ Q, float* __restrict__ K, float* __restrict__ V)
{
    int gid = blockIdx.x * blockDim.x + threadIdx.x;
    const int total = BB * SS * (NH + 2 * GG) * 64;
    if (gid >= total) return;

    int p  = gid & 63;
    int t  = gid >> 6;
    int hh = t % 36;   t /= 36;
    int s  = t % SS;
    int b  = t / SS;

    const size_t row = (size_t)(b * SS + s) * NQKV;

    int col, dstidx;
    float* dst;
    bool do_rope;
    if (hh < NH) {                 // q
        col = hh * HD + 2 * p;
        dst = Q;
        dstidx = ((b * NH + hh) * SS + s) * HD + 2 * p;
        do_rope = (p < 32);
    } else if (hh < NH + GG) {     // k
        int g = hh - NH;
        col = NH * HD + g * HD + 2 * p;
        dst = K;
        dstidx = ((b * GG + g) * SS + s) * HD + 2 * p;
        do_rope = (p < 32);
    } else {                       // v
        int g = hh - NH - GG;
        col = NH * HD + GG * HD + g * HD + 2 * p;
        dst = V;
        dstidx = ((b * GG + g) * SS + s) * HD + 2 * p;
        do_rope = false;
    }

    float2 x = *(const float2*)(qkv + row + col);
    if (do_rope) {
        const float2 c = *(const float2*)(rope + ((size_t)(s * BB + b) * 32 + p) * 2);
        float o0 = x.x * c.x - x.y * c.y;
        float o1 = x.y * c.x + x.x * c.y;
        x.x = o0; x.y = o1;
    }
    *(float2*)(dst + dstidx) = x;
}

// =============================================================================
// Causal flash attention, fp32. Grid: (S/64, B*NH). Block: 256 threads.
// Per CTA: 64 query rows. Thread (ty,tx) in 16x16 grid: 4x4 score frag,
// 4 rows x 8 cols O frag (cols = tx + 16*cc).
// SMEM: Qst[128][65] (d-major, transposed), Kst[128][65], Vs[64][128],
//       Pst[64][65] (transposed P: [col][row]).
// =============================================================================
#define ATT_SMEM_FLOATS (128*65 + 128*65 + 64*128 + 64*65)

__global__ void __launch_bounds__(256) attn_kernel(
    const float* __restrict__ Q, const float* __restrict__ K,
    const float* __restrict__ V, float* __restrict__ ctx)
{
    extern __shared__ float sm[];
    float* Qst = sm;                    // [128][65]
    float* Kst = Qst + 128 * 65;        // [128][65]
    float* Vs  = Kst + 128 * 65;        // [64][128]
    float* Pst = Vs  + 64 * 128;        // [64][65]  (P transposed: [kcol][qrow])

    const int qt   = blockIdx.x;
    const int head = blockIdx.y;
    const int b = head >> 5;
    const int h = head & 31;
    const int g = h >> 4;               // NH/G = 16

    const float* Qbase = Q + ((size_t)head * SS + qt * 64) * HD;
    const float* Kbase = K + ((size_t)(b * GG + g) * SS) * HD;
    const float* Vbase = V + ((size_t)(b * GG + g) * SS) * HD;

    const int tid  = threadIdx.x;
    const int lane = tid & 31;
    const int d4   = lane * 4;
    const int rw   = tid >> 5;
    const int tx   = tid & 15;
    const int ty   = tid >> 4;

    // Load Q tile transposed: Qst[d][r]
#pragma unroll
    for (int pass = 0; pass < 8; pass++) {
        int r = pass * 8 + rw;
        float4 q = *(const float4*)(Qbase + r * HD + d4);
        Qst[(d4 + 0) * 65 + r] = q.x;
        Qst[(d4 + 1) * 65 + r] = q.y;
        Qst[(d4 + 2) * 65 + r] = q.z;
        Qst[(d4 + 3) * 65 + r] = q.w;
    }

    const float NEGINF = -__int_as_float(0x7f800000);
    float m_run[4], l_run[4];
    float o[4][8];
#pragma unroll
    for (int i = 0; i < 4; i++) {
        m_run[i] = NEGINF;
        l_run[i] = 0.0f;
#pragma unroll
        for (int c = 0; c < 8; c++) o[i][c] = 0.0f;
    }

    const float scale = 0.08838834764831845f;  // 1/sqrt(128)

    for (int kt = 0; kt <= qt; kt++) {
        __syncthreads();   // previous iteration done reading Kst/Vs (also orders Q load)
        // Load K tile transposed + V tile
#pragma unroll
        for (int pass = 0; pass < 8; pass++) {
            int r = pass * 8 + rw;
            float4 kk = *(const float4*)(Kbase + (size_t)(kt * 64 + r) * HD + d4);
            Kst[(d4 + 0) * 65 + r] = kk.x;
            Kst[(d4 + 1) * 65 + r] = kk.y;
            Kst[(d4 + 2) * 65 + r] = kk.z;
            Kst[(d4 + 3) * 65 + r] = kk.w;
            float4 vv = *(const float4*)(Vbase + (size_t)(kt * 64 + r) * HD + d4);
            *(float4*)(Vs + r * 128 + d4) = vv;
        }
        __syncthreads();

        // Scores S[64,64] = Q @ K^T
        float s[4][4];
#pragma unroll
        for (int i = 0; i < 4; i++)
#pragma unroll
            for (int j = 0; j < 4; j++) s[i][j] = 0.0f;

#pragma unroll 4
        for (int d = 0; d < 128; d++) {
            float qr[4], kr[4];
#pragma unroll
            for (int i = 0; i < 4; i++) qr[i] = Qst[d * 65 + ty * 4 + i];
#pragma unroll
            for (int j = 0; j < 4; j++) kr[j] = Kst[d * 65 + tx * 4 + j];
#pragma unroll
            for (int i = 0; i < 4; i++)
#pragma unroll
                for (int j = 0; j < 4; j++)
                    s[i][j] += qr[i] * kr[j];
        }

        const bool diag = (kt == qt);
#pragma unroll
        for (int i = 0; i < 4; i++) {
            const int qrow = ty * 4 + i;  // local row
            float rowmax = NEGINF;
#pragma unroll
            for (int j = 0; j < 4; j++) {
                float val = s[i][j] * scale;
                if (diag && (tx * 4 + j > qrow)) val = NEGINF;
                s[i][j] = val;
                rowmax = fmaxf(rowmax, val);
            }
            // reduce across the 16 tx lanes (lane = (ty&1)*16 + tx)
#pragma unroll
            for (int off = 8; off >= 1; off >>= 1)
                rowmax = fmaxf(rowmax, __shfl_xor_sync(0xffffffffu, rowmax, off));

            float mnew = fmaxf(m_run[i], rowmax);
            float rowsum = 0.0f;
#pragma unroll
            for (int j = 0; j < 4; j++) {
                float pexp = __expf(s[i][j] - mnew);
                s[i][j] = pexp;
                rowsum += pexp;
            }
#pragma unroll
            for (int off = 8; off >= 1; off >>= 1)
                rowsum += __shfl_xor_sync(0xffffffffu, rowsum, off);

            float alpha = __expf(m_run[i] - mnew);
            l_run[i] = l_run[i] * alpha + rowsum;
            m_run[i] = mnew;
#pragma unroll
            for (int c = 0; c < 8; c++) o[i][c] *= alpha;
        }

        // Write P transposed: Pst[kcol][qrow]
#pragma unroll
        for (int i = 0; i < 4; i++)
#pragma unroll
            for (int j = 0; j < 4; j++)
                Pst[(tx * 4 + j) * 65 + ty * 4 + i] = s[i][j];
        __syncthreads();

        // O += P @ V : O[r][c], c = tx + 16*cc
#pragma unroll 2
        for (int j = 0; j < 64; j++) {
            float pr[4], vr[8];
#pragma unroll
            for (int i = 0; i < 4; i++) pr[i] = Pst[j * 65 + ty * 4 + i];
#pragma unroll
            for (int c = 0; c < 8; c++) vr[c] = Vs[j * 128 + tx + 16 * c];
#pragma unroll
            for (int i = 0; i < 4; i++)
#pragma unroll
                for (int c = 0; c < 8; c++)
                    o[i][c] += pr[i] * vr[c];
        }
    }

    // Normalize and write ctx[B,S,NH*HD]
#pragma unroll
    for (int i = 0; i < 4; i++) {
        float inv_l = 1.0f / l_run[i];
        int srow = qt * 64 + ty * 4 + i;
        size_t base = ((size_t)(b * SS + srow)) * HH + h * HD;
#pragma unroll
        for (int c = 0; c < 8; c++)
            ctx[base + tx + 16 * c] = o[i][c] * inv_l;
    }
}

// =============================================================================
// Host launcher
// =============================================================================
extern "C" void kernel_launch(void* const* d_in, const int* in_sizes, int n_in,
                              void* d_out, int out_size)
{
    (void)in_sizes; (void)n_in; (void)out_size;
    const float* hidden  = (const float*)d_in[0];
    const float* rope    = (const float*)d_in[1];
    const float* w_qkv   = (const float*)d_in[2];
    const float* b_qkv   = (const float*)d_in[3];
    const float* w_dense = (const float*)d_in[4];
    float* out = (float*)d_out;

    float *qkv, *q, *k, *v, *ctx;
    cudaGetSymbolAddress((void**)&qkv, g_qkv);
    cudaGetSymbolAddress((void**)&q,   g_q);
    cudaGetSymbolAddress((void**)&k,   g_k);
    cudaGetSymbolAddress((void**)&v,   g_v);
    cudaGetSymbolAddress((void**)&ctx, g_ctx);

    // 1) QKV GEMM + bias
    sgemm_kernel<<<dim3(NQKV / 128, MROWS / 128), 256>>>(
        hidden, w_qkv, b_qkv, qkv, MROWS, NQKV, HH);

    // 2) RoPE + scatter to head-major layouts
    {
        const int total = BB * SS * (NH + 2 * GG) * 64;
        rope_scatter_kernel<<<(total + 255) / 256, 256>>>(qkv, rope, q, k, v);
    }

    // 3) Causal flash attention
    {
        const int smem = ATT_SMEM_FLOATS * (int)sizeof(float);
        cudaFuncSetAttribute(attn_kernel,
                             cudaFuncAttributeMaxDynamicSharedMemorySize, smem);
        attn_kernel<<<dim3(SS / 64, BB * NH), 256, smem>>>(q, k, v, ctx);
    }

    // 4) Dense GEMM
    sgemm_kernel<<<dim3(HH / 128, MROWS / 128), 256>>>(
        ctx, w_dense, nullptr, out, MROWS, HH, HH);
}

// round 3
// speedup vs baseline: 1.6349x; 1.6349x over previous
#include <cuda_runtime.h>
#include <cuda_bf16.h>
#include <cstdint>

// Problem constants
#define BB 2
#define SS 1024
#define HH 4096
#define NH 32
#define GG 2
#define HD 128
#define NQKV 4608            // NH*HD + 2*G*HD
#define MROWS (BB*SS)        // 2048
#define KDIM 4096

// ---------------- scratch (static device globals; no allocs allowed) ----------
__device__ float g_qkv[MROWS * NQKV];          // [2048, 4608]
__device__ float g_q  [BB * NH * SS * HD];     // [B,NH,S,HD]
__device__ float g_k  [BB * GG * SS * HD];     // [B,G,S,HD]
__device__ float g_v  [BB * GG * SS * HD];     // [B,G,S,HD]
__device__ float g_ctx[MROWS * HH];            // [2048, 4096]

__device__ __nv_bfloat16 g_ah [MROWS * KDIM];  // hidden hi
__device__ __nv_bfloat16 g_al [MROWS * KDIM];  // hidden lo
__device__ __nv_bfloat16 g_wqh[KDIM * NQKV];   // w_qkv hi   [K,N]
__device__ __nv_bfloat16 g_wql[KDIM * NQKV];   // w_qkv lo
__device__ __nv_bfloat16 g_wdh[KDIM * HH];     // w_dense hi [K,N]
__device__ __nv_bfloat16 g_wdl[KDIM * HH];     // w_dense lo
__device__ __nv_bfloat16 g_ch [MROWS * KDIM];  // ctx hi
__device__ __nv_bfloat16 g_cl [MROWS * KDIM];  // ctx lo

// =============================================================================
// helpers
// =============================================================================
__device__ __forceinline__ uint32_t smem_to_u32(const void* p) {
    uint32_t a;
    asm("{ .reg .u64 t; cvta.to.shared.u64 t, %1; cvt.u32.u64 %0, t; }" : "=r"(a) : "l"(p));
    return a;
}

#define CP_ASYNC16(dst, src) \
    asm volatile("cp.async.cg.shared.global [%0], [%1], 16;" :: "r"(dst), "l"(src) : "memory")
#define CP_COMMIT() asm volatile("cp.async.commit_group;" ::: "memory")
template <int N> __device__ __forceinline__ void cp_wait() {
    asm volatile("cp.async.wait_group %0;" :: "n"(N) : "memory");
}

__device__ __forceinline__ void ldmatrix_x4(uint32_t* r, uint32_t addr) {
    asm volatile("ldmatrix.sync.aligned.m8n8.x4.shared.b16 {%0,%1,%2,%3}, [%4];"
                 : "=r"(r[0]), "=r"(r[1]), "=r"(r[2]), "=r"(r[3]) : "r"(addr));
}
__device__ __forceinline__ void ldmatrix_x2t(uint32_t* r, uint32_t addr) {
    asm volatile("ldmatrix.sync.aligned.m8n8.x2.trans.shared.b16 {%0,%1}, [%2];"
                 : "=r"(r[0]), "=r"(r[1]) : "r"(addr));
}
__device__ __forceinline__ void mma_16816(float* c, const uint32_t* a, const uint32_t* b) {
    asm volatile(
        "mma.sync.aligned.m16n8k16.row.col.f32.bf16.bf16.f32 "
        "{%0,%1,%2,%3}, {%4,%5,%6,%7}, {%8,%9}, {%0,%1,%2,%3};"
        : "+f"(c[0]), "+f"(c[1]), "+f"(c[2]), "+f"(c[3])
        : "r"(a[0]), "r"(a[1]), "r"(a[2]), "r"(a[3]), "r"(b[0]), "r"(b[1]));
}

// =============================================================================
// Conversion kernel: fp32 -> (hi, lo) bf16, elementwise (also used for weights;
// mma.sync takes B k-major so no transpose needed)
// =============================================================================
__global__ void __launch_bounds__(256) convert_hilo_kernel(
    const float* __restrict__ in, __nv_bfloat16* __restrict__ hi,
    __nv_bfloat16* __restrict__ lo, int n4)
{
    int i = blockIdx.x * blockDim.x + threadIdx.x;
    if (i >= n4) return;
    float4 x = ((const float4*)in)[i];
    __nv_bfloat16 h0 = __float2bfloat16(x.x);
    __nv_bfloat16 h1 = __float2bfloat16(x.y);
    __nv_bfloat16 h2 = __float2bfloat16(x.z);
    __nv_bfloat16 h3 = __float2bfloat16(x.w);
    ((__nv_bfloat162*)hi)[i * 2 + 0] = __halves2bfloat162(h0, h1);
    ((__nv_bfloat162*)hi)[i * 2 + 1] = __halves2bfloat162(h2, h3);
    ((__nv_bfloat162*)lo)[i * 2 + 0] = __halves2bfloat162(
        __float2bfloat16(x.x - __bfloat162float(h0)),
        __float2bfloat16(x.y - __bfloat162float(h1)));
    ((__nv_bfloat162*)lo)[i * 2 + 1] = __halves2bfloat162(
        __float2bfloat16(x.z - __bfloat162float(h2)),
        __float2bfloat16(x.w - __bfloat162float(h3)));
}

// =============================================================================
// mma.sync bf16 3-term split GEMM: C[M,N] = A[M,K] @ B[K,N] (+bias)
// A: Ah/Al [M,4096] bf16 row-major. B: Bh/Bl [4096,N] bf16 row-major.
// 3 segments: Ah*Bh + Al*Bh + Ah*Bl.
// Tile 128x128, BK=32, 3-stage cp.async pipeline, 8 warps (2x4), each 64x32.
// =============================================================================
#define GBM 128
#define GBN 128
#define GBK 32
#define GSTAGES 3
#define AS_ROWB 80                 // bytes per A smem row (32 bf16 + pad)
#define BS_ROWB 272                // bytes per B smem row (128 bf16 + pad)
#define AS_BYTES (GBM * AS_ROWB)   // 10240
#define BS_BYTES (GBK * BS_ROWB)   // 8704
#define STAGE_B (AS_BYTES + BS_BYTES)
#define GEMM_SMEM (GSTAGES * STAGE_B)
#define NIT (3 * (KDIM / GBK))     // 384

__global__ void __launch_bounds__(256) gemm_bf16x3_kernel(
    const __nv_bfloat16* __restrict__ Ah, const __nv_bfloat16* __restrict__ Al,
    const __nv_bfloat16* __restrict__ Bh, const __nv_bfloat16* __restrict__ Bl,
    const float* __restrict__ bias, float* __restrict__ C, int ldn)
{
    extern __shared__ char smraw[];
    const uint32_t sbase = smem_to_u32(smraw);
    const int tid  = threadIdx.x;
    const int lane = tid & 31;
    const int wid  = tid >> 5;
    const int wm   = wid & 1;      // 0..1 -> 64-row half
    const int wn   = wid >> 1;     // 0..3 -> 32-col quarter
    const int bm = blockIdx.y * GBM;
    const int bn = blockIdx.x * GBN;

    float acc[4][4][4];
#pragma unroll
    for (int mi = 0; mi < 4; mi++)
#pragma unroll
        for (int ni = 0; ni < 4; ni++)
#pragma unroll
            for (int t = 0; t < 4; t++) acc[mi][ni][t] = 0.0f;

    // ---- loader (each thread: 2 A chunks + 2 B chunks of 16B) ----
    auto load_stage = [&](int stage, int chunk) {
        const int seg = chunk >> 7;
        const int kc  = (chunk & 127) * GBK;
        const __nv_bfloat16* Ap = (seg == 1) ? Al : Ah;
        const __nv_bfloat16* Bp = (seg == 2) ? Bl : Bh;
        const uint32_t as = sbase + stage * STAGE_B;
        const uint32_t bs = as + AS_BYTES;
#pragma unroll
        for (int r = 0; r < 2; r++) {
            const int ch = tid + r * 256;
            const int row = ch >> 2, cc = ch & 3;
            CP_ASYNC16(as + row * AS_ROWB + cc * 16,
                       Ap + (size_t)(bm + row) * KDIM + kc + cc * 8);
        }
#pragma unroll
        for (int r = 0; r < 2; r++) {
            const int ch = tid + r * 256;
            const int row = ch >> 4, cc = ch & 15;
            CP_ASYNC16(bs + row * BS_ROWB + cc * 16,
                       Bp + (size_t)(kc + row) * ldn + bn + cc * 8);
        }
    };

    // prefetch
#pragma unroll
    for (int s = 0; s < GSTAGES - 1; s++) {
        load_stage(s, s);
        CP_COMMIT();
    }

    const int arow = lane & 15;
    const int acol8 = (lane >> 4) * 8;

    for (int it = 0; it < NIT; it++) {
        cp_wait<GSTAGES - 2>();
        __syncthreads();

        const int ls = it + GSTAGES - 1;
        if (ls < NIT) load_stage(ls % GSTAGES, ls);
        CP_COMMIT();

        const int st = it % GSTAGES;
        const uint32_t as = sbase + st * STAGE_B;
        const uint32_t bs = as + AS_BYTES;

#pragma unroll
        for (int ks = 0; ks < 2; ks++) {
            uint32_t a[4][4];
#pragma unroll
            for (int mi = 0; mi < 4; mi++) {
                const int row = wm * 64 + mi * 16 + arow;
                ldmatrix_x4(a[mi], as + row * AS_ROWB + (ks * 16 + acol8) * 2);
            }
            uint32_t b[4][2];
#pragma unroll
            for (int ni = 0; ni < 4; ni++) {
                const int row = ks * 16 + arow;
                ldmatrix_x2t(b[ni], bs + row * BS_ROWB + (wn * 32 + ni * 8) * 2);
            }
#pragma unroll
            for (int mi = 0; mi < 4; mi++)
#pragma unroll
                for (int ni = 0; ni < 4; ni++)
                    mma_16816(acc[mi][ni], a[mi], b[ni]);
        }
        __syncthreads();
    }

    // ---- epilogue ----
#pragma unroll
    for (int mi = 0; mi < 4; mi++) {
#pragma unroll
        for (int ni = 0; ni < 4; ni++) {
            const int r0 = bm + wm * 64 + mi * 16 + (lane >> 2);
            const int c  = bn + wn * 32 + ni * 8 + (lane & 3) * 2;
            float2 v0 = make_float2(acc[mi][ni][0], acc[mi][ni][1]);
            float2 v1 = make_float2(acc[mi][ni][2], acc[mi][ni][3]);
            if (bias) {
                const float2 bz = *(const float2*)(bias + c);
                v0.x += bz.x; v0.y += bz.y;
                v1.x += bz.x; v1.y += bz.y;
            }
            *(float2*)(C + (size_t)r0 * ldn + c) = v0;
            *(float2*)(C + (size_t)(r0 + 8) * ldn + c) = v1;
        }
    }
}

// =============================================================================
// RoPE + scatter
// =============================================================================
__global__ void __launch_bounds__(256) rope_scatter_kernel(
    const float* __restrict__ qkv, const float* __restrict__ rope,
    float* __restrict__ Q, float* __restrict__ K, float* __restrict__ V)
{
    int gid = blockIdx.x * blockDim.x + threadIdx.x;
    const int total = BB * SS * (NH + 2 * GG) * 64;
    if (gid >= total) return;

    int p  = gid & 63;
    int t  = gid >> 6;
    int hh = t % 36;   t /= 36;
    int s  = t % SS;
    int b  = t / SS;

    const size_t row = (size_t)(b * SS + s) * NQKV;

    int col, dstidx;
    float* dst;
    bool do_rope;
    if (hh < NH) {
        col = hh * HD + 2 * p;
        dst = Q;
        dstidx = ((b * NH + hh) * SS + s) * HD + 2 * p;
        do_rope = (p < 32);
    } else if (hh < NH + GG) {
        int g = hh - NH;
        col = NH * HD + g * HD + 2 * p;
        dst = K;
        dstidx = ((b * GG + g) * SS + s) * HD + 2 * p;
        do_rope = (p < 32);
    } else {
        int g = hh - NH - GG;
        col = NH * HD + GG * HD + g * HD + 2 * p;
        dst = V;
        dstidx = ((b * GG + g) * SS + s) * HD + 2 * p;
        do_rope = false;
    }

    float2 x = *(const float2*)(qkv + row + col);
    if (do_rope) {
        const float2 c = *(const float2*)(rope + ((size_t)(s * BB + b) * 32 + p) * 2);
        float o0 = x.x * c.x - x.y * c.y;
        float o1 = x.y * c.x + x.x * c.y;
        x.x = o0; x.y = o1;
    }
    *(float2*)(dst + dstidx) = x;
}

// =============================================================================
// Causal flash attention, fp32 (unchanged)
// =============================================================================
#define ATT_SMEM_FLOATS (128*65 + 128*65 + 64*128 + 64*65)

__global__ void __launch_bounds__(256) attn_kernel(
    const float* __restrict__ Q, const float* __restrict__ K,
    const float* __restrict__ V, float* __restrict__ ctx)
{
    extern __shared__ float sm[];
    float* Qst = sm;
    float* Kst = Qst + 128 * 65;
    float* Vs  = Kst + 128 * 65;
    float* Pst = Vs  + 64 * 128;

    const int qt   = blockIdx.x;
    const int head = blockIdx.y;
    const int b = head >> 5;
    const int h = head & 31;
    const int g = h >> 4;

    const float* Qbase = Q + ((size_t)head * SS + qt * 64) * HD;
    const float* Kbase = K + ((size_t)(b * GG + g) * SS) * HD;
    const float* Vbase = V + ((size_t)(b * GG + g) * SS) * HD;

    const int tid  = threadIdx.x;
    const int lane = tid & 31;
    const int d4   = lane * 4;
    const int rw   = tid >> 5;
    const int tx   = tid & 15;
    const int ty   = tid >> 4;

#pragma unroll
    for (int pass = 0; pass < 8; pass++) {
        int r = pass * 8 + rw;
        float4 q = *(const float4*)(Qbase + r * HD + d4);
        Qst[(d4 + 0) * 65 + r] = q.x;
        Qst[(d4 + 1) * 65 + r] = q.y;
        Qst[(d4 + 2) * 65 + r] = q.z;
        Qst[(d4 + 3) * 65 + r] = q.w;
    }

    const float NEGINF = -__int_as_float(0x7f800000);
    float m_run[4], l_run[4];
    float o[4][8];
#pragma unroll
    for (int i = 0; i < 4; i++) {
        m_run[i] = NEGINF;
        l_run[i] = 0.0f;
#pragma unroll
        for (int c = 0; c < 8; c++) o[i][c] = 0.0f;
    }

    const float scale = 0.08838834764831845f;

    for (int kt = 0; kt <= qt; kt++) {
        __syncthreads();
#pragma unroll
        for (int pass = 0; pass < 8; pass++) {
            int r = pass * 8 + rw;
            float4 kk = *(const float4*)(Kbase + (size_t)(kt * 64 + r) * HD + d4);
            Kst[(d4 + 0) * 65 + r] = kk.x;
            Kst[(d4 + 1) * 65 + r] = kk.y;
            Kst[(d4 + 2) * 65 + r] = kk.z;
            Kst[(d4 + 3) * 65 + r] = kk.w;
            float4 vv = *(const float4*)(Vbase + (size_t)(kt * 64 + r) * HD + d4);
            *(float4*)(Vs + r * 128 + d4) = vv;
        }
        __syncthreads();

        float s[4][4];
#pragma unroll
        for (int i = 0; i < 4; i++)
#pragma unroll
            for (int j = 0; j < 4; j++) s[i][j] = 0.0f;

#pragma unroll 4
        for (int d = 0; d < 128; d++) {
            float qr[4], kr[4];
#pragma unroll
            for (int i = 0; i < 4; i++) qr[i] = Qst[d * 65 + ty * 4 + i];
#pragma unroll
            for (int j = 0; j < 4; j++) kr[j] = Kst[d * 65 + tx * 4 + j];
#pragma unroll
            for (int i = 0; i < 4; i++)
#pragma unroll
                for (int j = 0; j < 4; j++)
                    s[i][j] += qr[i] * kr[j];
        }

        const bool diag = (kt == qt);
#pragma unroll
        for (int i = 0; i < 4; i++) {
            const int qrow = ty * 4 + i;
            float rowmax = NEGINF;
#pragma unroll
            for (int j = 0; j < 4; j++) {
                float val = s[i][j] * scale;
                if (diag && (tx * 4 + j > qrow)) val = NEGINF;
                s[i][j] = val;
                rowmax = fmaxf(rowmax, val);
            }
#pragma unroll
            for (int off = 8; off >= 1; off >>= 1)
                rowmax = fmaxf(rowmax, __shfl_xor_sync(0xffffffffu, rowmax, off));

            float mnew = fmaxf(m_run[i], rowmax);
            float rowsum = 0.0f;
#pragma unroll
            for (int j = 0; j < 4; j++) {
                float pexp = __expf(s[i][j] - mnew);
                s[i][j] = pexp;
                rowsum += pexp;
            }
#pragma unroll
            for (int off = 8; off >= 1; off >>= 1)
                rowsum += __shfl_xor_sync(0xffffffffu, rowsum, off);

            float alpha = __expf(m_run[i] - mnew);
            l_run[i] = l_run[i] * alpha + rowsum;
            m_run[i] = mnew;
#pragma unroll
            for (int c = 0; c < 8; c++) o[i][c] *= alpha;
        }

#pragma unroll
        for (int i = 0; i < 4; i++)
#pragma unroll
            for (int j = 0; j < 4; j++)
                Pst[(tx * 4 + j) * 65 + ty * 4 + i] = s[i][j];
        __syncthreads();

#pragma unroll 2
        for (int j = 0; j < 64; j++) {
            float pr[4], vr[8];
#pragma unroll
            for (int i = 0; i < 4; i++) pr[i] = Pst[j * 65 + ty * 4 + i];
#pragma unroll
            for (int c = 0; c < 8; c++) vr[c] = Vs[j * 128 + tx + 16 * c];
#pragma unroll
            for (int i = 0; i < 4; i++)
#pragma unroll
                for (int c = 0; c < 8; c++)
                    o[i][c] += pr[i] * vr[c];
        }
    }

#pragma unroll
    for (int i = 0; i < 4; i++) {
        float inv_l = 1.0f / l_run[i];
        int srow = qt * 64 + ty * 4 + i;
        size_t base = ((size_t)(b * SS + srow)) * HH + h * HD;
#pragma unroll
        for (int c = 0; c < 8; c++)
            ctx[base + tx + 16 * c] = o[i][c] * inv_l;
    }
}

// =============================================================================
// Host launcher
// =============================================================================
extern "C" void kernel_launch(void* const* d_in, const int* in_sizes, int n_in,
                              void* d_out, int out_size)
{
    (void)in_sizes; (void)n_in; (void)out_size;
    const float* hidden  = (const float*)d_in[0];
    const float* rope    = (const float*)d_in[1];
    const float* w_qkv   = (const float*)d_in[2];
    const float* b_qkv   = (const float*)d_in[3];
    const float* w_dense = (const float*)d_in[4];
    float* out = (float*)d_out;

    float *qkv, *q, *k, *v, *ctx;
    __nv_bfloat16 *ah, *al, *wqh, *wql, *wdh, *wdl, *ch, *cl;
    cudaGetSymbolAddress((void**)&qkv, g_qkv);
    cudaGetSymbolAddress((void**)&q,   g_q);
    cudaGetSymbolAddress((void**)&k,   g_k);
    cudaGetSymbolAddress((void**)&v,   g_v);
    cudaGetSymbolAddress((void**)&ctx, g_ctx);
    cudaGetSymbolAddress((void**)&ah,  g_ah);
    cudaGetSymbolAddress((void**)&al,  g_al);
    cudaGetSymbolAddress((void**)&wqh, g_wqh);
    cudaGetSymbolAddress((void**)&wql, g_wql);
    cudaGetSymbolAddress((void**)&wdh, g_wdh);
    cudaGetSymbolAddress((void**)&wdl, g_wdl);
    cudaGetSymbolAddress((void**)&ch,  g_ch);
    cudaGetSymbolAddress((void**)&cl,  g_cl);

    cudaFuncSetAttribute(gemm_bf16x3_kernel,
                         cudaFuncAttributeMaxDynamicSharedMemorySize, GEMM_SMEM);
    cudaFuncSetAttribute(attn_kernel,
                         cudaFuncAttributeMaxDynamicSharedMemorySize,
                         ATT_SMEM_FLOATS * (int)sizeof(float));

    // 1) split-precision conversions (elementwise; no transpose needed)
    {
        int n4 = MROWS * KDIM / 4;
        convert_hilo_kernel<<<(n4 + 255) / 256, 256>>>(hidden, ah, al, n4);
    }
    {
        int n4 = KDIM * NQKV / 4;
        convert_hilo_kernel<<<(n4 + 255) / 256, 256>>>(w_qkv, wqh, wql, n4);
    }
    {
        int n4 = KDIM * HH / 4;
        convert_hilo_kernel<<<(n4 + 255) / 256, 256>>>(w_dense, wdh, wdl, n4);
    }

    // 2) QKV GEMM (mma.sync bf16x3) + bias
    gemm_bf16x3_kernel<<<dim3(NQKV / GBN, MROWS / GBM), 256, GEMM_SMEM>>>(
        ah, al, wqh, wql, b_qkv, qkv, NQKV);

    // 3) RoPE + scatter
    {
        const int total = BB * SS * (NH + 2 * GG) * 64;
        rope_scatter_kernel<<<(total + 255) / 256, 256>>>(qkv, rope, q, k, v);
    }

    // 4) attention (fp32 flash)
    attn_kernel<<<dim3(SS / 64, BB * NH), 256, ATT_SMEM_FLOATS * (int)sizeof(float)>>>(q, k, v, ctx);

    // 5) ctx conversion + dense GEMM
    {
        int n4 = MROWS * KDIM / 4;
        convert_hilo_kernel<<<(n4 + 255) / 256, 256>>>(ctx, ch, cl, n4);
    }
    gemm_bf16x3_kernel<<<dim3(HH / GBN, MROWS / GBM), 256, GEMM_SMEM>>>(
        ch, cl, wdh, wdl, nullptr, out, HH);
}

// round 5
// speedup vs baseline: 2.3771x; 1.4540x over previous
#include <cuda_runtime.h>
#include <cuda_bf16.h>
#include <cuda_fp16.h>
#include <cstdint>

// Problem constants
#define BB 2
#define SS 1024
#define HH 4096
#define NH 32
#define GG 2
#define HD 128
#define NQKV 4608            // NH*HD + 2*G*HD
#define MROWS (BB*SS)        // 2048
#define KDIM 4096

// ---------------- scratch (static device globals) ----------------------------
__device__ float g_qkv[MROWS * NQKV];          // [2048, 4608] fp32
__device__ __half g_q [BB * NH * SS * HD];     // [B,NH,S,HD] fp16 (pre-scaled)
__device__ __half g_k [BB * GG * SS * HD];     // [B,G,S,HD] fp16
__device__ __half g_v [BB * GG * SS * HD];     // [B,G,S,HD] fp16

__device__ __nv_bfloat16 g_ah [MROWS * KDIM];  // hidden hi
__device__ __nv_bfloat16 g_al [MROWS * KDIM];  // hidden lo
__device__ __nv_bfloat16 g_wqh[KDIM * NQKV];   // w_qkv hi   [K,N]
__device__ __nv_bfloat16 g_wql[KDIM * NQKV];   // w_qkv lo
__device__ __nv_bfloat16 g_wdh[KDIM * HH];     // w_dense hi [K,N]
__device__ __nv_bfloat16 g_wdl[KDIM * HH];     // w_dense lo
__device__ __nv_bfloat16 g_ch [MROWS * KDIM];  // ctx hi (written by attention)
__device__ __nv_bfloat16 g_cl [MROWS * KDIM];  // ctx lo

// =============================================================================
// helpers
// =============================================================================
__device__ __forceinline__ uint32_t smem_to_u32(const void* p) {
    uint32_t a;
    asm("{ .reg .u64 t; cvta.to.shared.u64 t, %1; cvt.u32.u64 %0, t; }" : "=r"(a) : "l"(p));
    return a;
}

__device__ __forceinline__ uint32_t pack_half2(float lo, float hi) {
    __half2 h = __floats2half2_rn(lo, hi);
    uint32_t u;
    asm("mov.b32 %0, %1;" : "=r"(u) : "r"(*reinterpret_cast<uint32_t*>(&h)));
    return u;
}

#define CP_ASYNC16(dst, src) \
    asm volatile("cp.async.cg.shared.global [%0], [%1], 16;" :: "r"(dst), "l"(src) : "memory")
#define CP_COMMIT() asm volatile("cp.async.commit_group;" ::: "memory")
template <int N> __device__ __forceinline__ void cp_wait() {
    asm volatile("cp.async.wait_group %0;" :: "n"(N) : "memory");
}

__device__ __forceinline__ void ldmatrix_x4(uint32_t* r, uint32_t addr) {
    asm volatile("ldmatrix.sync.aligned.m8n8.x4.shared.b16 {%0,%1,%2,%3}, [%4];"
                 : "=r"(r[0]), "=r"(r[1]), "=r"(r[2]), "=r"(r[3]) : "r"(addr));
}
__device__ __forceinline__ void ldmatrix_x4t(uint32_t* r, uint32_t addr) {
    asm volatile("ldmatrix.sync.aligned.m8n8.x4.trans.shared.b16 {%0,%1,%2,%3}, [%4];"
                 : "=r"(r[0]), "=r"(r[1]), "=r"(r[2]), "=r"(r[3]) : "r"(addr));
}
__device__ __forceinline__ void mma_bf16(float* c, const uint32_t* a, const uint32_t* b) {
    asm volatile(
        "mma.sync.aligned.m16n8k16.row.col.f32.bf16.bf16.f32 "
        "{%0,%1,%2,%3}, {%4,%5,%6,%7}, {%8,%9}, {%0,%1,%2,%3};"
        : "+f"(c[0]), "+f"(c[1]), "+f"(c[2]), "+f"(c[3])
        : "r"(a[0]), "r"(a[1]), "r"(a[2]), "r"(a[3]), "r"(b[0]), "r"(b[1]));
}
__device__ __forceinline__ void mma_f16(float* c, const uint32_t* a, const uint32_t* b) {
    asm volatile(
        "mma.sync.aligned.m16n8k16.row.col.f32.f16.f16.f32 "
        "{%0,%1,%2,%3}, {%4,%5,%6,%7}, {%8,%9}, {%0,%1,%2,%3};"
        : "+f"(c[0]), "+f"(c[1]), "+f"(c[2]), "+f"(c[3])
        : "r"(a[0]), "r"(a[1]), "r"(a[2]), "r"(a[3]), "r"(b[0]), "r"(b[1]));
}

// =============================================================================
// Conversion: fp32 -> (hi, lo) bf16, elementwise
// =============================================================================
__global__ void __launch_bounds__(256) convert_hilo_kernel(
    const float* __restrict__ in, __nv_bfloat16* __restrict__ hi,
    __nv_bfloat16* __restrict__ lo, int n4)
{
    int i = blockIdx.x * blockDim.x + threadIdx.x;
    if (i >= n4) return;
    float4 x = ((const float4*)in)[i];
    __nv_bfloat16 h0 = __float2bfloat16(x.x);
    __nv_bfloat16 h1 = __float2bfloat16(x.y);
    __nv_bfloat16 h2 = __float2bfloat16(x.z);
    __nv_bfloat16 h3 = __float2bfloat16(x.w);
    ((__nv_bfloat162*)hi)[i * 2 + 0] = __halves2bfloat162(h0, h1);
    ((__nv_bfloat162*)hi)[i * 2 + 1] = __halves2bfloat162(h2, h3);
    ((__nv_bfloat162*)lo)[i * 2 + 0] = __halves2bfloat162(
        __float2bfloat16(x.x - __bfloat162float(h0)),
        __float2bfloat16(x.y - __bfloat162float(h1)));
    ((__nv_bfloat162*)lo)[i * 2 + 1] = __halves2bfloat162(
        __float2bfloat16(x.z - __bfloat162float(h2)),
        __float2bfloat16(x.w - __bfloat162float(h3)));
}

// =============================================================================
// mma.sync bf16 3-term split GEMM: C[M,N] = A[M,K]@B[K,N] (+bias)
// CTA tile 128x256, BK=32, 4-stage cp.async, 8 warps (2x4) each 64x64.
// One __syncthreads per mainloop iteration.
// =============================================================================
#define GBM 128
#define GBN 256
#define GBK 32
#define GSTAGES 4
#define AS_ROWB 80                   // 32 bf16 = 64B + 16 pad
#define BS_ROWB 528                  // 256 bf16 = 512B + 16 pad
#define AS_BYTES (GBM * AS_ROWB)     // 10240
#define BS_BYTES (GBK * BS_ROWB)     // 16896
#define STAGE_B (AS_BYTES + BS_BYTES)
#define GEMM_SMEM (GSTAGES * STAGE_B)
#define NIT (3 * (KDIM / GBK))       // 384

__global__ void __launch_bounds__(256, 1) gemm_bf16x3_kernel(
    const __nv_bfloat16* __restrict__ Ah, const __nv_bfloat16* __restrict__ Al,
    const __nv_bfloat16* __restrict__ Bh, const __nv_bfloat16* __restrict__ Bl,
    const float* __restrict__ bias, float* __restrict__ C, int ldn)
{
    extern __shared__ char smraw[];
    const uint32_t sbase = smem_to_u32(smraw);
    const int tid  = threadIdx.x;
    const int lane = tid & 31;
    const int wid  = tid >> 5;
    const int wm   = wid & 1;      // row half (64)
    const int wn   = wid >> 1;     // col quarter (64)
    const int bm = blockIdx.y * GBM;
    const int bn = blockIdx.x * GBN;

    float acc[4][8][4];
#pragma unroll
    for (int mi = 0; mi < 4; mi++)
#pragma unroll
        for (int ni = 0; ni < 8; ni++)
#pragma unroll
            for (int t = 0; t < 4; t++) acc[mi][ni][t] = 0.0f;

    auto load_stage = [&](int stage, int chunk) {
        const int seg = chunk >> 7;
        const int kc  = (chunk & 127) * GBK;
        const __nv_bfloat16* Ap = (seg == 1) ? Al : Ah;
        const __nv_bfloat16* Bp = (seg == 2) ? Bl : Bh;
        const uint32_t as = sbase + stage * STAGE_B;
        const uint32_t bs = as + AS_BYTES;
#pragma unroll
        for (int r = 0; r < 2; r++) {
            const int ch = tid + r * 256;
            const int row = ch >> 2, cc = ch & 3;
            CP_ASYNC16(as + row * AS_ROWB + cc * 16,
                       Ap + (size_t)(bm + row) * KDIM + kc + cc * 8);
        }
#pragma unroll
        for (int r = 0; r < 4; r++) {
            const int ch = tid + r * 256;
            const int row = ch >> 5, cc = ch & 31;
            CP_ASYNC16(bs + row * BS_ROWB + cc * 16,
                       Bp + (size_t)(kc + row) * ldn + bn + cc * 8);
        }
    };

#pragma unroll
    for (int s = 0; s < GSTAGES - 1; s++) {
        load_stage(s, s);
        CP_COMMIT();
    }

    for (int it = 0; it < NIT; it++) {
        cp_wait<GSTAGES - 2>();
        __syncthreads();

        const int ls = it + GSTAGES - 1;
        if (ls < NIT) load_stage(ls & (GSTAGES - 1), ls);
        CP_COMMIT();

        const uint32_t as = sbase + (it & (GSTAGES - 1)) * STAGE_B;
        const uint32_t bs = as + AS_BYTES;

#pragma unroll
        for (int ks = 0; ks < 2; ks++) {
            uint32_t a[4][4];
#pragma unroll
            for (int mi = 0; mi < 4; mi++) {
                const int row = wm * 64 + mi * 16 + (lane & 15);
                ldmatrix_x4(a[mi], as + row * AS_ROWB + (ks * 16 + (lane >> 4) * 8) * 2);
            }
            uint32_t bfr[8][2];
#pragma unroll
            for (int nb = 0; nb < 4; nb++) {
                uint32_t bv[4];
                const int row = ks * 16 + ((lane >> 3) & 1) * 8 + (lane & 7);
                const int col = wn * 64 + nb * 16 + (lane >> 4) * 8;
                ldmatrix_x4t(bv, bs + row * BS_ROWB + col * 2);
                bfr[nb * 2 + 0][0] = bv[0]; bfr[nb * 2 + 0][1] = bv[1];
                bfr[nb * 2 + 1][0] = bv[2]; bfr[nb * 2 + 1][1] = bv[3];
            }
#pragma unroll
            for (int mi = 0; mi < 4; mi++)
#pragma unroll
                for (int ni = 0; ni < 8; ni++)
                    mma_bf16(acc[mi][ni], a[mi], bfr[ni]);
        }
    }

    // epilogue
#pragma unroll
    for (int mi = 0; mi < 4; mi++) {
#pragma unroll
        for (int ni = 0; ni < 8; ni++) {
            const int r0 = bm + wm * 64 + mi * 16 + (lane >> 2);
            const int c  = bn + wn * 64 + ni * 8 + (lane & 3) * 2;
            float2 v0 = make_float2(acc[mi][ni][0], acc[mi][ni][1]);
            float2 v1 = make_float2(acc[mi][ni][2], acc[mi][ni][3]);
            if (bias) {
                const float2 bz = *(const float2*)(bias + c);
                v0.x += bz.x; v0.y += bz.y;
                v1.x += bz.x; v1.y += bz.y;
            }
            *(float2*)(C + (size_t)r0 * ldn + c) = v0;
            *(float2*)(C + (size_t)(r0 + 8) * ldn + c) = v1;
        }
    }
}

// =============================================================================
// RoPE + scatter -> fp16 Q (pre-scaled by 1/sqrt(HD)), K, V
// =============================================================================
__global__ void __launch_bounds__(256) rope_scatter_kernel(
    const float* __restrict__ qkv, const float* __restrict__ rope,
    __half* __restrict__ Q, __half* __restrict__ K, __half* __restrict__ V)
{
    int gid = blockIdx.x * blockDim.x + threadIdx.x;
    const int total = BB * SS * (NH + 2 * GG) * 64;
    if (gid >= total) return;

    int p  = gid & 63;
    int t  = gid >> 6;
    int hh = t % 36;   t /= 36;
    int s  = t % SS;
    int b  = t / SS;

    const size_t row = (size_t)(b * SS + s) * NQKV;
    const float qscale = 0.08838834764831845f;

    int col, dstidx;
    __half* dst;
    bool do_rope;
    float sc = 1.0f;
    if (hh < NH) {
        col = hh * HD + 2 * p;
        dst = Q;
        dstidx = ((b * NH + hh) * SS + s) * HD + 2 * p;
        do_rope = (p < 32);
        sc = qscale;
    } else if (hh < NH + GG) {
        int g = hh - NH;
        col = NH * HD + g * HD + 2 * p;
        dst = K;
        dstidx = ((b * GG + g) * SS + s) * HD + 2 * p;
        do_rope = (p < 32);
    } else {
        int g = hh - NH - GG;
        col = NH * HD + GG * HD + g * HD + 2 * p;
        dst = V;
        dstidx = ((b * GG + g) * SS + s) * HD + 2 * p;
        do_rope = false;
    }

    float2 x = *(const float2*)(qkv + row + col);
    if (do_rope) {
        const float2 c = *(const float2*)(rope + ((size_t)(s * BB + b) * 32 + p) * 2);
        float o0 = x.x * c.x - x.y * c.y;
        float o1 = x.y * c.x + x.x * c.y;
        x.x = o0; x.y = o1;
    }
    __half2 hv = __floats2half2_rn(x.x * sc, x.y * sc);
    *(__half2*)(dst + dstidx) = hv;
}

// =============================================================================
// Flash attention, fp16 mma.sync. Grid (S/64, B*NH). 128 threads (4 warps).
// Warp w owns q-rows [16w,16w+16). Output written as hi/lo bf16 split for the
// dense GEMM.
// =============================================================================
#define AT_ROWB 272  // 128 fp16 = 256B + 16 pad

__global__ void __launch_bounds__(128) attn_mma_kernel(
    const __half* __restrict__ Q, const __half* __restrict__ K,
    const __half* __restrict__ V,
    __nv_bfloat16* __restrict__ Chi, __nv_bfloat16* __restrict__ Clo)
{
    extern __shared__ char smc[];
    const uint32_t sq = smem_to_u32(smc);
    const uint32_t sk = sq + 64 * AT_ROWB;
    const uint32_t sv = sk + 64 * AT_ROWB;

    const int qt   = blockIdx.x;
    const int head = blockIdx.y;
    const int b = head >> 5;
    const int h = head & 31;
    const int g = h >> 4;

    const __half* Qb = Q + ((size_t)head * SS + qt * 64) * HD;
    const __half* Kb = K + ((size_t)(b * GG + g) * SS) * HD;
    const __half* Vb = V + ((size_t)(b * GG + g) * SS) * HD;

    const int tid = threadIdx.x;
    const int lane = tid & 31;
    const int wid = tid >> 5;

    // load Q tile (64 x 128 fp16)
#pragma unroll
    for (int i = 0; i < 8; i++) {
        const int id = tid + i * 128;
        const int row = id >> 4, col = id & 15;
        CP_ASYNC16(sq + row * AT_ROWB + col * 16, Qb + row * HD + col * 8);
    }
    CP_COMMIT(); cp_wait<0>(); __syncthreads();

    // preload Q a-frags
    uint32_t aq[8][4];
    {
        const int row = wid * 16 + (lane & 15);
        const int c8 = (lane >> 4) * 8;
#pragma unroll
        for (int ks = 0; ks < 8; ks++)
            ldmatrix_x4(aq[ks], sq + row * AT_ROWB + (ks * 16 + c8) * 2);
    }

    float m_run[2] = {-1e30f, -1e30f};
    float l_run[2] = {0.0f, 0.0f};
    float o[16][4];
#pragma unroll
    for (int n = 0; n < 16; n++)
#pragma unroll
        for (int t = 0; t < 4; t++) o[n][t] = 0.0f;

    for (int kt = 0; kt <= qt; kt++) {
        __syncthreads();  // everyone done reading sk/sv of previous iter
#pragma unroll
        for (int i = 0; i < 8; i++) {
            const int id = tid + i * 128;
            const int row = id >> 4, col = id & 15;
            CP_ASYNC16(sk + row * AT_ROWB + col * 16,
                       Kb + (size_t)(kt * 64 + row) * HD + col * 8);
            CP_ASYNC16(sv + row * AT_ROWB + col * 16,
                       Vb + (size_t)(kt * 64 + row) * HD + col * 8);
        }
        CP_COMMIT(); cp_wait<0>(); __syncthreads();

        // ---- S = Q K^T (s[8][4], n over 64 k-positions) ----
        float s[8][4];
#pragma unroll
        for (int j = 0; j < 8; j++)
#pragma unroll
            for (int t = 0; t < 4; t++) s[j][t] = 0.0f;

#pragma unroll
        for (int ks = 0; ks < 8; ks++) {
#pragma unroll
            for (int nb = 0; nb < 4; nb++) {
                uint32_t bv[4];
                const int row = nb * 16 + (lane & 15);
                const int col = ks * 16 + (lane >> 4) * 8;
                ldmatrix_x4(bv, sk + row * AT_ROWB + col * 2);
                uint32_t b0[2] = {bv[0], bv[2]};
                uint32_t b1[2] = {bv[1], bv[3]};
                mma_f16(s[nb * 2 + 0], aq[ks], b0);
                mma_f16(s[nb * 2 + 1], aq[ks], b1);
            }
        }

        // ---- online softmax on fragments ----
        if (kt == qt) {
            // causal mask within diagonal tile
            const int rbase = wid * 16 + (lane >> 2);
#pragma unroll
            for (int j = 0; j < 8; j++) {
#pragma unroll
                for (int t = 0; t < 4; t++) {
                    const int cc = j * 8 + (lane & 3) * 2 + (t & 1);
                    const int rr = rbase + (t >> 1) * 8;
                    if (cc > rr) s[j][t] = -1e30f;
                }
            }
        }
        float mx0 = -1e30f, mx1 = -1e30f;
#pragma unroll
        for (int j = 0; j < 8; j++) {
            mx0 = fmaxf(mx0, fmaxf(s[j][0], s[j][1]));
            mx1 = fmaxf(mx1, fmaxf(s[j][2], s[j][3]));
        }
        mx0 = fmaxf(mx0, __shfl_xor_sync(0xffffffffu, mx0, 1));
        mx0 = fmaxf(mx0, __shfl_xor_sync(0xffffffffu, mx0, 2));
        mx1 = fmaxf(mx1, __shfl_xor_sync(0xffffffffu, mx1, 1));
        mx1 = fmaxf(mx1, __shfl_xor_sync(0xffffffffu, mx1, 2));

        const float mn0 = fmaxf(m_run[0], mx0);
        const float mn1 = fmaxf(m_run[1], mx1);
        const float al0 = __expf(m_run[0] - mn0);
        const float al1 = __expf(m_run[1] - mn1);

        float sum0 = 0.0f, sum1 = 0.0f;
#pragma unroll
        for (int j = 0; j < 8; j++) {
            s[j][0] = __expf(s[j][0] - mn0);
            s[j][1] = __expf(s[j][1] - mn0);
            s[j][2] = __expf(s[j][2] - mn1);
            s[j][3] = __expf(s[j][3] - mn1);
            sum0 += s[j][0] + s[j][1];
            sum1 += s[j][2] + s[j][3];
        }
        sum0 += __shfl_xor_sync(0xffffffffu, sum0, 1);
        sum0 += __shfl_xor_sync(0xffffffffu, sum0, 2);
        sum1 += __shfl_xor_sync(0xffffffffu, sum1, 1);
        sum1 += __shfl_xor_sync(0xffffffffu, sum1, 2);

        l_run[0] = l_run[0] * al0 + sum0;
        l_run[1] = l_run[1] * al1 + sum1;
        m_run[0] = mn0;
        m_run[1] = mn1;

#pragma unroll
        for (int n = 0; n < 16; n++) {
            o[n][0] *= al0; o[n][1] *= al0;
            o[n][2] *= al1; o[n][3] *= al1;
        }

        // ---- O += P V ----
#pragma unroll
        for (int kk = 0; kk < 4; kk++) {
            uint32_t ap[4];
            ap[0] = pack_half2(s[2 * kk][0], s[2 * kk][1]);
            ap[1] = pack_half2(s[2 * kk][2], s[2 * kk][3]);
            ap[2] = pack_half2(s[2 * kk + 1][0], s[2 * kk + 1][1]);
            ap[3] = pack_half2(s[2 * kk + 1][2], s[2 * kk + 1][3]);
#pragma unroll
            for (int nb = 0; nb < 8; nb++) {
                uint32_t bv[4];
                const int row = kk * 16 + ((lane >> 3) & 1) * 8 + (lane & 7);
                const int col = nb * 16 + (lane >> 4) * 8;
                ldmatrix_x4t(bv, sv + row * AT_ROWB + col * 2);
                uint32_t b0[2] = {bv[0], bv[1]};
                uint32_t b1[2] = {bv[2], bv[3]};
                mma_f16(o[nb * 2 + 0], ap, b0);
                mma_f16(o[nb * 2 + 1], ap, b1);
            }
        }
    }

    // ---- write output as hi/lo bf16 into dense-GEMM A buffers ----
    const float inv0 = 1.0f / l_run[0];
    const float inv1 = 1.0f / l_run[1];
    const int r1 = qt * 64 + wid * 16 + (lane >> 2);
#pragma unroll
    for (int n = 0; n < 16; n++) {
        const int hd0 = n * 8 + (lane & 3) * 2;
        const size_t i1 = (size_t)(b * SS + r1) * HH + h * HD + hd0;
        const size_t i2 = (size_t)(b * SS + r1 + 8) * HH + h * HD + hd0;
        float v00 = o[n][0] * inv0, v01 = o[n][1] * inv0;
        float v10 = o[n][2] * inv1, v11 = o[n][3] * inv1;
        __nv_bfloat16 h00 = __float2bfloat16(v00), h01 = __float2bfloat16(v01);
        __nv_bfloat16 h10 = __float2bfloat16(v10), h11 = __float2bfloat16(v11);
        *(__nv_bfloat162*)(Chi + i1) = __halves2bfloat162(h00, h01);
        *(__nv_bfloat162*)(Chi + i2) = __halves2bfloat162(h10, h11);
        *(__nv_bfloat162*)(Clo + i1) = __halves2bfloat162(
            __float2bfloat16(v00 - __bfloat162float(h00)),
            __float2bfloat16(v01 - __bfloat162float(h01)));
        *(__nv_bfloat162*)(Clo + i2) = __halves2bfloat162(
            __float2bfloat16(v10 - __bfloat162float(h10)),
            __float2bfloat16(v11 - __bfloat162float(h11)));
    }
}

// =============================================================================
// Host launcher
// =============================================================================
extern "C" void kernel_launch(void* const* d_in, const int* in_sizes, int n_in,
                              void* d_out, int out_size)
{
    (void)in_sizes; (void)n_in; (void)out_size;
    const float* hidden  = (const float*)d_in[0];
    const float* rope    = (const float*)d_in[1];
    const float* w_qkv   = (const float*)d_in[2];
    const float* b_qkv   = (const float*)d_in[3];
    const float* w_dense = (const float*)d_in[4];
    float* out = (float*)d_out;

    float* qkv;
    __half *q, *k, *v;
    __nv_bfloat16 *ah, *al, *wqh, *wql, *wdh, *wdl, *ch, *cl;
    cudaGetSymbolAddress((void**)&qkv, g_qkv);
    cudaGetSymbolAddress((void**)&q,   g_q);
    cudaGetSymbolAddress((void**)&k,   g_k);
    cudaGetSymbolAddress((void**)&v,   g_v);
    cudaGetSymbolAddress((void**)&ah,  g_ah);
    cudaGetSymbolAddress((void**)&al,  g_al);
    cudaGetSymbolAddress((void**)&wqh, g_wqh);
    cudaGetSymbolAddress((void**)&wql, g_wql);
    cudaGetSymbolAddress((void**)&wdh, g_wdh);
    cudaGetSymbolAddress((void**)&wdl, g_wdl);
    cudaGetSymbolAddress((void**)&ch,  g_ch);
    cudaGetSymbolAddress((void**)&cl,  g_cl);

    cudaFuncSetAttribute(gemm_bf16x3_kernel,
                         cudaFuncAttributeMaxDynamicSharedMemorySize, GEMM_SMEM);
    cudaFuncSetAttribute(attn_mma_kernel,
                         cudaFuncAttributeMaxDynamicSharedMemorySize, 3 * 64 * AT_ROWB);

    // 1) hi/lo conversions
    {
        int n4 = MROWS * KDIM / 4;
        convert_hilo_kernel<<<(n4 + 255) / 256, 256>>>(hidden, ah, al, n4);
    }
    {
        int n4 = KDIM * NQKV / 4;
        convert_hilo_kernel<<<(n4 + 255) / 256, 256>>>(w_qkv, wqh, wql, n4);
    }
    {
        int n4 = KDIM * HH / 4;
        convert_hilo_kernel<<<(n4 + 255) / 256, 256>>>(w_dense, wdh, wdl, n4);
    }

    // 2) QKV GEMM + bias
    gemm_bf16x3_kernel<<<dim3(NQKV / GBN, MROWS / GBM), 256, GEMM_SMEM>>>(
        ah, al, wqh, wql, b_qkv, qkv, NQKV);

    // 3) RoPE + scatter to fp16 head-major
    {
        const int total = BB * SS * (NH + 2 * GG) * 64;
        rope_scatter_kernel<<<(total + 255) / 256, 256>>>(qkv, rope, q, k, v);
    }

    // 4) fp16 tensor-core flash attention (writes hi/lo bf16 ctx)
    attn_mma_kernel<<<dim3(SS / 64, BB * NH), 128, 3 * 64 * AT_ROWB>>>(q, k, v, ch, cl);

    // 5) dense GEMM
    gemm_bf16x3_kernel<<<dim3(HH / GBN, MROWS / GBM), 256, GEMM_SMEM>>>(
        ch, cl, wdh, wdl, nullptr, out, HH);
}

// round 6
// speedup vs baseline: 2.7219x; 1.1451x over previous
#include <cuda_runtime.h>
#include <cuda_bf16.h>
#include <cuda_fp16.h>
#include <cstdint>

// Problem constants
#define BB 2
#define SS 1024
#define HH 4096
#define NH 32
#define GG 2
#define HD 128
#define NQKV 4608            // NH*HD + 2*G*HD
#define MROWS (BB*SS)        // 2048
#define KDIM 4096

// ---------------- scratch (static device globals) ----------------------------
__device__ float g_qkv[MROWS * NQKV];          // [2048, 4608] fp32
__device__ __half g_q [BB * NH * SS * HD];     // [B,NH,S,HD] fp16 (pre-scaled)
__device__ __half g_k [BB * GG * SS * HD];     // [B,G,S,HD] fp16
__device__ __half g_v [BB * GG * SS * HD];     // [B,G,S,HD] fp16

__device__ __nv_bfloat16 g_ah [MROWS * KDIM];  // hidden hi
__device__ __nv_bfloat16 g_al [MROWS * KDIM];  // hidden lo
__device__ __nv_bfloat16 g_wqh[KDIM * NQKV];   // w_qkv hi   [K,N]
__device__ __nv_bfloat16 g_wql[KDIM * NQKV];   // w_qkv lo
__device__ __nv_bfloat16 g_wdh[KDIM * HH];     // w_dense hi [K,N]
__device__ __nv_bfloat16 g_wdl[KDIM * HH];     // w_dense lo
__device__ __nv_bfloat16 g_ch [MROWS * KDIM];  // ctx hi (written by attention)
__device__ __nv_bfloat16 g_cl [MROWS * KDIM];  // ctx lo

// =============================================================================
// helpers
// =============================================================================
__device__ __forceinline__ uint32_t smem_to_u32(const void* p) {
    uint32_t a;
    asm("{ .reg .u64 t; cvta.to.shared.u64 t, %1; cvt.u32.u64 %0, t; }" : "=r"(a) : "l"(p));
    return a;
}

__device__ __forceinline__ uint32_t pack_half2(float lo, float hi) {
    __half2 h = __floats2half2_rn(lo, hi);
    uint32_t u;
    asm("mov.b32 %0, %1;" : "=r"(u) : "r"(*reinterpret_cast<uint32_t*>(&h)));
    return u;
}

#define CP_ASYNC16(dst, src) \
    asm volatile("cp.async.cg.shared.global [%0], [%1], 16;" :: "r"(dst), "l"(src) : "memory")
#define CP_COMMIT() asm volatile("cp.async.commit_group;" ::: "memory")
template <int N> __device__ __forceinline__ void cp_wait() {
    asm volatile("cp.async.wait_group %0;" :: "n"(N) : "memory");
}

__device__ __forceinline__ void ldmatrix_x4(uint32_t* r, uint32_t addr) {
    asm volatile("ldmatrix.sync.aligned.m8n8.x4.shared.b16 {%0,%1,%2,%3}, [%4];"
                 : "=r"(r[0]), "=r"(r[1]), "=r"(r[2]), "=r"(r[3]) : "r"(addr));
}
__device__ __forceinline__ void ldmatrix_x4t(uint32_t* r, uint32_t addr) {
    asm volatile("ldmatrix.sync.aligned.m8n8.x4.trans.shared.b16 {%0,%1,%2,%3}, [%4];"
                 : "=r"(r[0]), "=r"(r[1]), "=r"(r[2]), "=r"(r[3]) : "r"(addr));
}
__device__ __forceinline__ void mma_bf16(float* c, const uint32_t* a, const uint32_t* b) {
    asm volatile(
        "mma.sync.aligned.m16n8k16.row.col.f32.bf16.bf16.f32 "
        "{%0,%1,%2,%3}, {%4,%5,%6,%7}, {%8,%9}, {%0,%1,%2,%3};"
        : "+f"(c[0]), "+f"(c[1]), "+f"(c[2]), "+f"(c[3])
        : "r"(a[0]), "r"(a[1]), "r"(a[2]), "r"(a[3]), "r"(b[0]), "r"(b[1]));
}
__device__ __forceinline__ void mma_f16(float* c, const uint32_t* a, const uint32_t* b) {
    asm volatile(
        "mma.sync.aligned.m16n8k16.row.col.f32.f16.f16.f32 "
        "{%0,%1,%2,%3}, {%4,%5,%6,%7}, {%8,%9}, {%0,%1,%2,%3};"
        : "+f"(c[0]), "+f"(c[1]), "+f"(c[2]), "+f"(c[3])
        : "r"(a[0]), "r"(a[1]), "r"(a[2]), "r"(a[3]), "r"(b[0]), "r"(b[1]));
}

// =============================================================================
// Conversion: fp32 -> (hi, lo) bf16, elementwise
// =============================================================================
__global__ void __launch_bounds__(256) convert_hilo_kernel(
    const float* __restrict__ in, __nv_bfloat16* __restrict__ hi,
    __nv_bfloat16* __restrict__ lo, int n4)
{
    int i = blockIdx.x * blockDim.x + threadIdx.x;
    if (i >= n4) return;
    float4 x = ((const float4*)in)[i];
    __nv_bfloat16 h0 = __float2bfloat16(x.x);
    __nv_bfloat16 h1 = __float2bfloat16(x.y);
    __nv_bfloat16 h2 = __float2bfloat16(x.z);
    __nv_bfloat16 h3 = __float2bfloat16(x.w);
    ((__nv_bfloat162*)hi)[i * 2 + 0] = __halves2bfloat162(h0, h1);
    ((__nv_bfloat162*)hi)[i * 2 + 1] = __halves2bfloat162(h2, h3);
    ((__nv_bfloat162*)lo)[i * 2 + 0] = __halves2bfloat162(
        __float2bfloat16(x.x - __bfloat162float(h0)),
        __float2bfloat16(x.y - __bfloat162float(h1)));
    ((__nv_bfloat162*)lo)[i * 2 + 1] = __halves2bfloat162(
        __float2bfloat16(x.z - __bfloat162float(h2)),
        __float2bfloat16(x.w - __bfloat162float(h3)));
}

// =============================================================================
// mma.sync bf16 3-term split GEMM v3: C[M,N] = A[M,K]@B[K,N] (+bias)
// CTA tile 128x128, BK=64, 3-stage cp.async, 8 warps (4x2) each 32x64.
// 2 CTAs per SM (4 warps/SMSP) to feed the tensor pipe.
// =============================================================================
#define GBM 128
#define GBN 128
#define GBK 64
#define GSTAGES 3
#define AS_ROWB 144                  // 64 bf16 = 128B + 16 pad
#define BS_ROWB 272                  // 128 bf16 = 256B + 16 pad
#define AS_BYTES (GBM * AS_ROWB)     // 18432
#define BS_BYTES (GBK * BS_ROWB)     // 17408
#define STAGE_B (AS_BYTES + BS_BYTES)// 35840
#define GEMM_SMEM (GSTAGES * STAGE_B)// 107520
#define NIT (3 * (KDIM / GBK))       // 192

__global__ void __launch_bounds__(256, 2) gemm_bf16x3_kernel(
    const __nv_bfloat16* __restrict__ Ah, const __nv_bfloat16* __restrict__ Al,
    const __nv_bfloat16* __restrict__ Bh, const __nv_bfloat16* __restrict__ Bl,
    const float* __restrict__ bias, float* __restrict__ C, int ldn)
{
    extern __shared__ char smraw[];
    const uint32_t sbase = smem_to_u32(smraw);
    const int tid  = threadIdx.x;
    const int lane = tid & 31;
    const int wid  = tid >> 5;
    const int wm   = wid & 3;      // 4 row-blocks of 32
    const int wn   = wid >> 2;     // 2 col-blocks of 64
    const int bm = blockIdx.y * GBM;
    const int bn = blockIdx.x * GBN;

    float acc[2][8][4];
#pragma unroll
    for (int mi = 0; mi < 2; mi++)
#pragma unroll
        for (int ni = 0; ni < 8; ni++)
#pragma unroll
            for (int t = 0; t < 4; t++) acc[mi][ni][t] = 0.0f;

    // loader: A 128x64 bf16 = 1024 chunks, B 64x128 bf16 = 1024 chunks; 8/thread
    auto load_stage = [&](int stage, int chunk) {
        const int seg = chunk >> 6;
        const int kc  = (chunk & 63) << 6;
        const __nv_bfloat16* Ap = (seg == 1) ? Al : Ah;
        const __nv_bfloat16* Bp = (seg == 2) ? Bl : Bh;
        const uint32_t as = sbase + stage * STAGE_B;
        const uint32_t bs = as + AS_BYTES;
#pragma unroll
        for (int r = 0; r < 4; r++) {
            const int ch = tid + r * 256;
            const int row = ch >> 3, cc = ch & 7;
            CP_ASYNC16(as + row * AS_ROWB + cc * 16,
                       Ap + (size_t)(bm + row) * KDIM + kc + cc * 8);
        }
#pragma unroll
        for (int r = 0; r < 4; r++) {
            const int ch = tid + r * 256;
            const int row = ch >> 4, cc = ch & 15;
            CP_ASYNC16(bs + row * BS_ROWB + cc * 16,
                       Bp + (size_t)(kc + row) * ldn + bn + cc * 8);
        }
    };

#pragma unroll
    for (int s = 0; s < GSTAGES - 1; s++) {
        load_stage(s, s);
        CP_COMMIT();
    }

    int stq = 0;  // stage cursor
    for (int it = 0; it < NIT; it++) {
        cp_wait<GSTAGES - 2>();
        __syncthreads();

        const int ls = it + GSTAGES - 1;
        const int wst = (stq + GSTAGES - 1) % GSTAGES;
        if (ls < NIT) load_stage(wst, ls);
        CP_COMMIT();

        const uint32_t as = sbase + stq * STAGE_B;
        const uint32_t bs = as + AS_BYTES;
        stq = (stq + 1) % GSTAGES;

#pragma unroll
        for (int ks = 0; ks < 4; ks++) {
            uint32_t a[2][4];
#pragma unroll
            for (int mi = 0; mi < 2; mi++) {
                const int row = wm * 32 + mi * 16 + (lane & 15);
                ldmatrix_x4(a[mi], as + row * AS_ROWB + (ks * 16 + (lane >> 4) * 8) * 2);
            }
            uint32_t bfr[8][2];
#pragma unroll
            for (int nb = 0; nb < 4; nb++) {
                uint32_t bv[4];
                const int row = ks * 16 + ((lane >> 3) & 1) * 8 + (lane & 7);
                const int col = wn * 64 + nb * 16 + (lane >> 4) * 8;
                ldmatrix_x4t(bv, bs + row * BS_ROWB + col * 2);
                bfr[nb * 2 + 0][0] = bv[0]; bfr[nb * 2 + 0][1] = bv[1];
                bfr[nb * 2 + 1][0] = bv[2]; bfr[nb * 2 + 1][1] = bv[3];
            }
#pragma unroll
            for (int mi = 0; mi < 2; mi++)
#pragma unroll
                for (int ni = 0; ni < 8; ni++)
                    mma_bf16(acc[mi][ni], a[mi], bfr[ni]);
        }
    }

    // epilogue
#pragma unroll
    for (int mi = 0; mi < 2; mi++) {
#pragma unroll
        for (int ni = 0; ni < 8; ni++) {
            const int r0 = bm + wm * 32 + mi * 16 + (lane >> 2);
            const int c  = bn + wn * 64 + ni * 8 + (lane & 3) * 2;
            float2 v0 = make_float2(acc[mi][ni][0], acc[mi][ni][1]);
            float2 v1 = make_float2(acc[mi][ni][2], acc[mi][ni][3]);
            if (bias) {
                const float2 bz = *(const float2*)(bias + c);
                v0.x += bz.x; v0.y += bz.y;
                v1.x += bz.x; v1.y += bz.y;
            }
            *(float2*)(C + (size_t)r0 * ldn + c) = v0;
            *(float2*)(C + (size_t)(r0 + 8) * ldn + c) = v1;
        }
    }
}

// =============================================================================
// RoPE + scatter -> fp16 Q (pre-scaled by 1/sqrt(HD)), K, V
// =============================================================================
__global__ void __launch_bounds__(256) rope_scatter_kernel(
    const float* __restrict__ qkv, const float* __restrict__ rope,
    __half* __restrict__ Q, __half* __restrict__ K, __half* __restrict__ V)
{
    int gid = blockIdx.x * blockDim.x + threadIdx.x;
    const int total = BB * SS * (NH + 2 * GG) * 64;
    if (gid >= total) return;

    int p  = gid & 63;
    int t  = gid >> 6;
    int hh = t % 36;   t /= 36;
    int s  = t % SS;
    int b  = t / SS;

    const size_t row = (size_t)(b * SS + s) * NQKV;
    const float qscale = 0.08838834764831845f;

    int col, dstidx;
    __half* dst;
    bool do_rope;
    float sc = 1.0f;
    if (hh < NH) {
        col = hh * HD + 2 * p;
        dst = Q;
        dstidx = ((b * NH + hh) * SS + s) * HD + 2 * p;
        do_rope = (p < 32);
        sc = qscale;
    } else if (hh < NH + GG) {
        int g = hh - NH;
        col = NH * HD + g * HD + 2 * p;
        dst = K;
        dstidx = ((b * GG + g) * SS + s) * HD + 2 * p;
        do_rope = (p < 32);
    } else {
        int g = hh - NH - GG;
        col = NH * HD + GG * HD + g * HD + 2 * p;
        dst = V;
        dstidx = ((b * GG + g) * SS + s) * HD + 2 * p;
        do_rope = false;
    }

    float2 x = *(const float2*)(qkv + row + col);
    if (do_rope) {
        const float2 c = *(const float2*)(rope + ((size_t)(s * BB + b) * 32 + p) * 2);
        float o0 = x.x * c.x - x.y * c.y;
        float o1 = x.y * c.x + x.x * c.y;
        x.x = o0; x.y = o1;
    }
    __half2 hv = __floats2half2_rn(x.x * sc, x.y * sc);
    *(__half2*)(dst + dstidx) = hv;
}

// =============================================================================
// Flash attention, fp16 mma.sync. Grid (S/64, B*NH). 128 threads (4 warps).
// =============================================================================
#define AT_ROWB 272  // 128 fp16 = 256B + 16 pad

__global__ void __launch_bounds__(128) attn_mma_kernel(
    const __half* __restrict__ Q, const __half* __restrict__ K,
    const __half* __restrict__ V,
    __nv_bfloat16* __restrict__ Chi, __nv_bfloat16* __restrict__ Clo)
{
    extern __shared__ char smc[];
    const uint32_t sq = smem_to_u32(smc);
    const uint32_t sk = sq + 64 * AT_ROWB;
    const uint32_t sv = sk + 64 * AT_ROWB;

    const int qt   = blockIdx.x;
    const int head = blockIdx.y;
    const int b = head >> 5;
    const int h = head & 31;
    const int g = h >> 4;

    const __half* Qb = Q + ((size_t)head * SS + qt * 64) * HD;
    const __half* Kb = K + ((size_t)(b * GG + g) * SS) * HD;
    const __half* Vb = V + ((size_t)(b * GG + g) * SS) * HD;

    const int tid = threadIdx.x;
    const int lane = tid & 31;
    const int wid = tid >> 5;

    // load Q tile (64 x 128 fp16)
#pragma unroll
    for (int i = 0; i < 8; i++) {
        const int id = tid + i * 128;
        const int row = id >> 4, col = id & 15;
        CP_ASYNC16(sq + row * AT_ROWB + col * 16, Qb + row * HD + col * 8);
    }
    CP_COMMIT(); cp_wait<0>(); __syncthreads();

    // preload Q a-frags
    uint32_t aq[8][4];
    {
        const int row = wid * 16 + (lane & 15);
        const int c8 = (lane >> 4) * 8;
#pragma unroll
        for (int ks = 0; ks < 8; ks++)
            ldmatrix_x4(aq[ks], sq + row * AT_ROWB + (ks * 16 + c8) * 2);
    }

    float m_run[2] = {-1e30f, -1e30f};
    float l_run[2] = {0.0f, 0.0f};
    float o[16][4];
#pragma unroll
    for (int n = 0; n < 16; n++)
#pragma unroll
        for (int t = 0; t < 4; t++) o[n][t] = 0.0f;

    for (int kt = 0; kt <= qt; kt++) {
        __syncthreads();
#pragma unroll
        for (int i = 0; i < 8; i++) {
            const int id = tid + i * 128;
            const int row = id >> 4, col = id & 15;
            CP_ASYNC16(sk + row * AT_ROWB + col * 16,
                       Kb + (size_t)(kt * 64 + row) * HD + col * 8);
            CP_ASYNC16(sv + row * AT_ROWB + col * 16,
                       Vb + (size_t)(kt * 64 + row) * HD + col * 8);
        }
        CP_COMMIT(); cp_wait<0>(); __syncthreads();

        // ---- S = Q K^T ----
        float s[8][4];
#pragma unroll
        for (int j = 0; j < 8; j++)
#pragma unroll
            for (int t = 0; t < 4; t++) s[j][t] = 0.0f;

#pragma unroll
        for (int ks = 0; ks < 8; ks++) {
#pragma unroll
            for (int nb = 0; nb < 4; nb++) {
                uint32_t bv[4];
                const int row = nb * 16 + (lane & 15);
                const int col = ks * 16 + (lane >> 4) * 8;
                ldmatrix_x4(bv, sk + row * AT_ROWB + col * 2);
                uint32_t b0[2] = {bv[0], bv[2]};
                uint32_t b1[2] = {bv[1], bv[3]};
                mma_f16(s[nb * 2 + 0], aq[ks], b0);
                mma_f16(s[nb * 2 + 1], aq[ks], b1);
            }
        }

        // ---- online softmax ----
        if (kt == qt) {
            const int rbase = wid * 16 + (lane >> 2);
#pragma unroll
            for (int j = 0; j < 8; j++) {
#pragma unroll
                for (int t = 0; t < 4; t++) {
                    const int cc = j * 8 + (lane & 3) * 2 + (t & 1);
                    const int rr = rbase + (t >> 1) * 8;
                    if (cc > rr) s[j][t] = -1e30f;
                }
            }
        }
        float mx0 = -1e30f, mx1 = -1e30f;
#pragma unroll
        for (int j = 0; j < 8; j++) {
            mx0 = fmaxf(mx0, fmaxf(s[j][0], s[j][1]));
            mx1 = fmaxf(mx1, fmaxf(s[j][2], s[j][3]));
        }
        mx0 = fmaxf(mx0, __shfl_xor_sync(0xffffffffu, mx0, 1));
        mx0 = fmaxf(mx0, __shfl_xor_sync(0xffffffffu, mx0, 2));
        mx1 = fmaxf(mx1, __shfl_xor_sync(0xffffffffu, mx1, 1));
        mx1 = fmaxf(mx1, __shfl_xor_sync(0xffffffffu, mx1, 2));

        const float mn0 = fmaxf(m_run[0], mx0);
        const float mn1 = fmaxf(m_run[1], mx1);
        const float al0 = __expf(m_run[0] - mn0);
        const float al1 = __expf(m_run[1] - mn1);

        float sum0 = 0.0f, sum1 = 0.0f;
#pragma unroll
        for (int j = 0; j < 8; j++) {
            s[j][0] = __expf(s[j][0] - mn0);
            s[j][1] = __expf(s[j][1] - mn0);
            s[j][2] = __expf(s[j][2] - mn1);
            s[j][3] = __expf(s[j][3] - mn1);
            sum0 += s[j][0] + s[j][1];
            sum1 += s[j][2] + s[j][3];
        }
        sum0 += __shfl_xor_sync(0xffffffffu, sum0, 1);
        sum0 += __shfl_xor_sync(0xffffffffu, sum0, 2);
        sum1 += __shfl_xor_sync(0xffffffffu, sum1, 1);
        sum1 += __shfl_xor_sync(0xffffffffu, sum1, 2);

        l_run[0] = l_run[0] * al0 + sum0;
        l_run[1] = l_run[1] * al1 + sum1;
        m_run[0] = mn0;
        m_run[1] = mn1;

#pragma unroll
        for (int n = 0; n < 16; n++) {
            o[n][0] *= al0; o[n][1] *= al0;
            o[n][2] *= al1; o[n][3] *= al1;
        }

        // ---- O += P V ----
#pragma unroll
        for (int kk = 0; kk < 4; kk++) {
            uint32_t ap[4];
            ap[0] = pack_half2(s[2 * kk][0], s[2 * kk][1]);
            ap[1] = pack_half2(s[2 * kk][2], s[2 * kk][3]);
            ap[2] = pack_half2(s[2 * kk + 1][0], s[2 * kk + 1][1]);
            ap[3] = pack_half2(s[2 * kk + 1][2], s[2 * kk + 1][3]);
#pragma unroll
            for (int nb = 0; nb < 8; nb++) {
                uint32_t bv[4];
                const int row = kk * 16 + ((lane >> 3) & 1) * 8 + (lane & 7);
                const int col = nb * 16 + (lane >> 4) * 8;
                ldmatrix_x4t(bv, sv + row * AT_ROWB + col * 2);
                uint32_t b0[2] = {bv[0], bv[1]};
                uint32_t b1[2] = {bv[2], bv[3]};
                mma_f16(o[nb * 2 + 0], ap, b0);
                mma_f16(o[nb * 2 + 1], ap, b1);
            }
        }
    }

    // ---- write output as hi/lo bf16 into dense-GEMM A buffers ----
    const float inv0 = 1.0f / l_run[0];
    const float inv1 = 1.0f / l_run[1];
    const int r1 = qt * 64 + wid * 16 + (lane >> 2);
#pragma unroll
    for (int n = 0; n < 16; n++) {
        const int hd0 = n * 8 + (lane & 3) * 2;
        const size_t i1 = (size_t)(b * SS + r1) * HH + h * HD + hd0;
        const size_t i2 = (size_t)(b * SS + r1 + 8) * HH + h * HD + hd0;
        float v00 = o[n][0] * inv0, v01 = o[n][1] * inv0;
        float v10 = o[n][2] * inv1, v11 = o[n][3] * inv1;
        __nv_bfloat16 h00 = __float2bfloat16(v00), h01 = __float2bfloat16(v01);
        __nv_bfloat16 h10 = __float2bfloat16(v10), h11 = __float2bfloat16(v11);
        *(__nv_bfloat162*)(Chi + i1) = __halves2bfloat162(h00, h01);
        *(__nv_bfloat162*)(Chi + i2) = __halves2bfloat162(h10, h11);
        *(__nv_bfloat162*)(Clo + i1) = __halves2bfloat162(
            __float2bfloat16(v00 - __bfloat162float(h00)),
            __float2bfloat16(v01 - __bfloat162float(h01)));
        *(__nv_bfloat162*)(Clo + i2) = __halves2bfloat162(
            __float2bfloat16(v10 - __bfloat162float(h10)),
            __float2bfloat16(v11 - __bfloat162float(h11)));
    }
}

// =============================================================================
// Host launcher
// =============================================================================
extern "C" void kernel_launch(void* const* d_in, const int* in_sizes, int n_in,
                              void* d_out, int out_size)
{
    (void)in_sizes; (void)n_in; (void)out_size;
    const float* hidden  = (const float*)d_in[0];
    const float* rope    = (const float*)d_in[1];
    const float* w_qkv   = (const float*)d_in[2];
    const float* b_qkv   = (const float*)d_in[3];
    const float* w_dense = (const float*)d_in[4];
    float* out = (float*)d_out;

    float* qkv;
    __half *q, *k, *v;
    __nv_bfloat16 *ah, *al, *wqh, *wql, *wdh, *wdl, *ch, *cl;
    cudaGetSymbolAddress((void**)&qkv, g_qkv);
    cudaGetSymbolAddress((void**)&q,   g_q);
    cudaGetSymbolAddress((void**)&k,   g_k);
    cudaGetSymbolAddress((void**)&v,   g_v);
    cudaGetSymbolAddress((void**)&ah,  g_ah);
    cudaGetSymbolAddress((void**)&al,  g_al);
    cudaGetSymbolAddress((void**)&wqh, g_wqh);
    cudaGetSymbolAddress((void**)&wql, g_wql);
    cudaGetSymbolAddress((void**)&wdh, g_wdh);
    cudaGetSymbolAddress((void**)&wdl, g_wdl);
    cudaGetSymbolAddress((void**)&ch,  g_ch);
    cudaGetSymbolAddress((void**)&cl,  g_cl);

    cudaFuncSetAttribute(gemm_bf16x3_kernel,
                         cudaFuncAttributeMaxDynamicSharedMemorySize, GEMM_SMEM);
    cudaFuncSetAttribute(attn_mma_kernel,
                         cudaFuncAttributeMaxDynamicSharedMemorySize, 3 * 64 * AT_ROWB);

    // 1) hi/lo conversions
    {
        int n4 = MROWS * KDIM / 4;
        convert_hilo_kernel<<<(n4 + 255) / 256, 256>>>(hidden, ah, al, n4);
    }
    {
        int n4 = KDIM * NQKV / 4;
        convert_hilo_kernel<<<(n4 + 255) / 256, 256>>>(w_qkv, wqh, wql, n4);
    }
    {
        int n4 = KDIM * HH / 4;
        convert_hilo_kernel<<<(n4 + 255) / 256, 256>>>(w_dense, wdh, wdl, n4);
    }

    // 2) QKV GEMM + bias
    gemm_bf16x3_kernel<<<dim3(NQKV / GBN, MROWS / GBM), 256, GEMM_SMEM>>>(
        ah, al, wqh, wql, b_qkv, qkv, NQKV);

    // 3) RoPE + scatter to fp16 head-major
    {
        const int total = BB * SS * (NH + 2 * GG) * 64;
        rope_scatter_kernel<<<(total + 255) / 256, 256>>>(qkv, rope, q, k, v);
    }

    // 4) fp16 tensor-core flash attention (writes hi/lo bf16 ctx)
    attn_mma_kernel<<<dim3(SS / 64, BB * NH), 128, 3 * 64 * AT_ROWB>>>(q, k, v, ch, cl);

    // 5) dense GEMM
    gemm_bf16x3_kernel<<<dim3(HH / GBN, MROWS / GBM), 256, GEMM_SMEM>>>(
        ch, cl, wdh, wdl, nullptr, out, HH);
}

// round 7
// speedup vs baseline: 6.7054x; 2.4635x over previous
#include <cuda_runtime.h>
#include <cuda_bf16.h>
#include <cuda_fp16.h>
#include <cstdint>

// Problem constants
#define BB 2
#define SS 1024
#define HH 4096
#define NH 32
#define GG 2
#define HD 128
#define NQKV 4608            // NH*HD + 2*G*HD
#define MROWS (BB*SS)        // 2048
#define KDIM 4096

// ---------------- scratch (static device globals) ----------------------------
__device__ float g_qkv[MROWS * NQKV];          // [2048, 4608] fp32
__device__ __half g_q [BB * NH * SS * HD];     // [B,NH,S,HD] fp16 (pre-scaled)
__device__ __half g_k [BB * GG * SS * HD];     // [B,G,S,HD] fp16
__device__ __half g_v [BB * GG * SS * HD];     // [B,G,S,HD] fp16

__device__ __half g_ah [MROWS * KDIM];         // hidden fp16
__device__ __half g_wq [KDIM * NQKV];          // w_qkv fp16 [K,N]
__device__ __half g_wd [KDIM * HH];            // w_dense fp16 [K,N]
__device__ __half g_ctx[MROWS * HH];           // ctx fp16 (written by attention)

// =============================================================================
// helpers
// =============================================================================
__device__ __forceinline__ uint32_t smem_to_u32(const void* p) {
    uint32_t a;
    asm("{ .reg .u64 t; cvta.to.shared.u64 t, %1; cvt.u32.u64 %0, t; }" : "=r"(a) : "l"(p));
    return a;
}

__device__ __forceinline__ uint32_t pack_half2(float lo, float hi) {
    __half2 h = __floats2half2_rn(lo, hi);
    uint32_t u;
    asm("mov.b32 %0, %1;" : "=r"(u) : "r"(*reinterpret_cast<uint32_t*>(&h)));
    return u;
}

#define CP_ASYNC16(dst, src) \
    asm volatile("cp.async.cg.shared.global [%0], [%1], 16;" :: "r"(dst), "l"(src) : "memory")
#define CP_COMMIT() asm volatile("cp.async.commit_group;" ::: "memory")
template <int N> __device__ __forceinline__ void cp_wait() {
    asm volatile("cp.async.wait_group %0;" :: "n"(N) : "memory");
}

__device__ __forceinline__ void ldmatrix_x4(uint32_t* r, uint32_t addr) {
    asm volatile("ldmatrix.sync.aligned.m8n8.x4.shared.b16 {%0,%1,%2,%3}, [%4];"
                 : "=r"(r[0]), "=r"(r[1]), "=r"(r[2]), "=r"(r[3]) : "r"(addr));
}
__device__ __forceinline__ void ldmatrix_x4t(uint32_t* r, uint32_t addr) {
    asm volatile("ldmatrix.sync.aligned.m8n8.x4.trans.shared.b16 {%0,%1,%2,%3}, [%4];"
                 : "=r"(r[0]), "=r"(r[1]), "=r"(r[2]), "=r"(r[3]) : "r"(addr));
}
__device__ __forceinline__ void mma_f16(float* c, const uint32_t* a, const uint32_t* b) {
    asm volatile(
        "mma.sync.aligned.m16n8k16.row.col.f32.f16.f16.f32 "
        "{%0,%1,%2,%3}, {%4,%5,%6,%7}, {%8,%9}, {%0,%1,%2,%3};"
        : "+f"(c[0]), "+f"(c[1]), "+f"(c[2]), "+f"(c[3])
        : "r"(a[0]), "r"(a[1]), "r"(a[2]), "r"(a[3]), "r"(b[0]), "r"(b[1]));
}

// =============================================================================
// Conversion: fp32 -> fp16, elementwise
// =============================================================================
__global__ void __launch_bounds__(256) convert_f16_kernel(
    const float* __restrict__ in, __half* __restrict__ out, int n4)
{
    int i = blockIdx.x * blockDim.x + threadIdx.x;
    if (i >= n4) return;
    float4 x = ((const float4*)in)[i];
    ((__half2*)out)[i * 2 + 0] = __floats2half2_rn(x.x, x.y);
    ((__half2*)out)[i * 2 + 1] = __floats2half2_rn(x.z, x.w);
}

// =============================================================================
// mma.sync fp16 single-pass GEMM: C[M,N] = A[M,K]@B[K,N] (+bias)
// CTA tile 128x128, BK=64, 3-stage cp.async, 8 warps (4x2) each 32x64.
// 2 CTAs per SM.
// =============================================================================
#define GBM 128
#define GBN 128
#define GBK 64
#define GSTAGES 3
#define AS_ROWB 144                  // 64 fp16 = 128B + 16 pad
#define BS_ROWB 272                  // 128 fp16 = 256B + 16 pad
#define AS_BYTES (GBM * AS_ROWB)     // 18432
#define BS_BYTES (GBK * BS_ROWB)     // 17408
#define STAGE_B (AS_BYTES + BS_BYTES)// 35840
#define GEMM_SMEM (GSTAGES * STAGE_B)// 107520
#define NIT (KDIM / GBK)             // 64

__global__ void __launch_bounds__(256, 2) gemm_f16_kernel(
    const __half* __restrict__ A, const __half* __restrict__ B,
    const float* __restrict__ bias, float* __restrict__ C, int ldn)
{
    extern __shared__ char smraw[];
    const uint32_t sbase = smem_to_u32(smraw);
    const int tid  = threadIdx.x;
    const int lane = tid & 31;
    const int wid  = tid >> 5;
    const int wm   = wid & 3;      // 4 row-blocks of 32
    const int wn   = wid >> 2;     // 2 col-blocks of 64
    const int bm = blockIdx.y * GBM;
    const int bn = blockIdx.x * GBN;

    float acc[2][8][4];
#pragma unroll
    for (int mi = 0; mi < 2; mi++)
#pragma unroll
        for (int ni = 0; ni < 8; ni++)
#pragma unroll
            for (int t = 0; t < 4; t++) acc[mi][ni][t] = 0.0f;

    auto load_stage = [&](int stage, int chunk) {
        const int kc = chunk << 6;
        const uint32_t as = sbase + stage * STAGE_B;
        const uint32_t bs = as + AS_BYTES;
#pragma unroll
        for (int r = 0; r < 4; r++) {
            const int ch = tid + r * 256;
            const int row = ch >> 3, cc = ch & 7;
            CP_ASYNC16(as + row * AS_ROWB + cc * 16,
                       A + (size_t)(bm + row) * KDIM + kc + cc * 8);
        }
#pragma unroll
        for (int r = 0; r < 4; r++) {
            const int ch = tid + r * 256;
            const int row = ch >> 4, cc = ch & 15;
            CP_ASYNC16(bs + row * BS_ROWB + cc * 16,
                       B + (size_t)(kc + row) * ldn + bn + cc * 8);
        }
    };

#pragma unroll
    for (int s = 0; s < GSTAGES - 1; s++) {
        load_stage(s, s);
        CP_COMMIT();
    }

    int stq = 0;
    for (int it = 0; it < NIT; it++) {
        cp_wait<GSTAGES - 2>();
        __syncthreads();

        const int ls = it + GSTAGES - 1;
        const int wst = (stq + GSTAGES - 1) % GSTAGES;
        if (ls < NIT) load_stage(wst, ls);
        CP_COMMIT();

        const uint32_t as = sbase + stq * STAGE_B;
        const uint32_t bs = as + AS_BYTES;
        stq = (stq + 1) % GSTAGES;

#pragma unroll
        for (int ks = 0; ks < 4; ks++) {
            uint32_t a[2][4];
#pragma unroll
            for (int mi = 0; mi < 2; mi++) {
                const int row = wm * 32 + mi * 16 + (lane & 15);
                ldmatrix_x4(a[mi], as + row * AS_ROWB + (ks * 16 + (lane >> 4) * 8) * 2);
            }
            uint32_t bfr[8][2];
#pragma unroll
            for (int nb = 0; nb < 4; nb++) {
                uint32_t bv[4];
                const int row = ks * 16 + ((lane >> 3) & 1) * 8 + (lane & 7);
                const int col = wn * 64 + nb * 16 + (lane >> 4) * 8;
                ldmatrix_x4t(bv, bs + row * BS_ROWB + col * 2);
                bfr[nb * 2 + 0][0] = bv[0]; bfr[nb * 2 + 0][1] = bv[1];
                bfr[nb * 2 + 1][0] = bv[2]; bfr[nb * 2 + 1][1] = bv[3];
            }
#pragma unroll
            for (int mi = 0; mi < 2; mi++)
#pragma unroll
                for (int ni = 0; ni < 8; ni++)
                    mma_f16(acc[mi][ni], a[mi], bfr[ni]);
        }
    }

    // epilogue
#pragma unroll
    for (int mi = 0; mi < 2; mi++) {
#pragma unroll
        for (int ni = 0; ni < 8; ni++) {
            const int r0 = bm + wm * 32 + mi * 16 + (lane >> 2);
            const int c  = bn + wn * 64 + ni * 8 + (lane & 3) * 2;
            float2 v0 = make_float2(acc[mi][ni][0], acc[mi][ni][1]);
            float2 v1 = make_float2(acc[mi][ni][2], acc[mi][ni][3]);
            if (bias) {
                const float2 bz = *(const float2*)(bias + c);
                v0.x += bz.x; v0.y += bz.y;
                v1.x += bz.x; v1.y += bz.y;
            }
            *(float2*)(C + (size_t)r0 * ldn + c) = v0;
            *(float2*)(C + (size_t)(r0 + 8) * ldn + c) = v1;
        }
    }
}

// =============================================================================
// RoPE + scatter -> fp16 Q (pre-scaled by 1/sqrt(HD)), K, V
// =============================================================================
__global__ void __launch_bounds__(256) rope_scatter_kernel(
    const float* __restrict__ qkv, const float* __restrict__ rope,
    __half* __restrict__ Q, __half* __restrict__ K, __half* __restrict__ V)
{
    int gid = blockIdx.x * blockDim.x + threadIdx.x;
    const int total = BB * SS * (NH + 2 * GG) * 64;
    if (gid >= total) return;

    int p  = gid & 63;
    int t  = gid >> 6;
    int hh = t % 36;   t /= 36;
    int s  = t % SS;
    int b  = t / SS;

    const size_t row = (size_t)(b * SS + s) * NQKV;
    const float qscale = 0.08838834764831845f;

    int col, dstidx;
    __half* dst;
    bool do_rope;
    float sc = 1.0f;
    if (hh < NH) {
        col = hh * HD + 2 * p;
        dst = Q;
        dstidx = ((b * NH + hh) * SS + s) * HD + 2 * p;
        do_rope = (p < 32);
        sc = qscale;
    } else if (hh < NH + GG) {
        int g = hh - NH;
        col = NH * HD + g * HD + 2 * p;
        dst = K;
        dstidx = ((b * GG + g) * SS + s) * HD + 2 * p;
        do_rope = (p < 32);
    } else {
        int g = hh - NH - GG;
        col = NH * HD + GG * HD + g * HD + 2 * p;
        dst = V;
        dstidx = ((b * GG + g) * SS + s) * HD + 2 * p;
        do_rope = false;
    }

    float2 x = *(const float2*)(qkv + row + col);
    if (do_rope) {
        const float2 c = *(const float2*)(rope + ((size_t)(s * BB + b) * 32 + p) * 2);
        float o0 = x.x * c.x - x.y * c.y;
        float o1 = x.y * c.x + x.x * c.y;
        x.x = o0; x.y = o1;
    }
    __half2 hv = __floats2half2_rn(x.x * sc, x.y * sc);
    *(__half2*)(dst + dstidx) = hv;
}

// =============================================================================
// Flash attention, fp16 mma.sync. Grid (S/64, B*NH). 128 threads (4 warps).
// Writes fp16 ctx for the dense GEMM.
// =============================================================================
#define AT_ROWB 272  // 128 fp16 = 256B + 16 pad

__global__ void __launch_bounds__(128) attn_mma_kernel(
    const __half* __restrict__ Q, const __half* __restrict__ K,
    const __half* __restrict__ V, __half* __restrict__ Ctx)
{
    extern __shared__ char smc[];
    const uint32_t sq = smem_to_u32(smc);
    const uint32_t sk = sq + 64 * AT_ROWB;
    const uint32_t sv = sk + 64 * AT_ROWB;

    const int qt   = blockIdx.x;
    const int head = blockIdx.y;
    const int b = head >> 5;
    const int h = head & 31;
    const int g = h >> 4;

    const __half* Qb = Q + ((size_t)head * SS + qt * 64) * HD;
    const __half* Kb = K + ((size_t)(b * GG + g) * SS) * HD;
    const __half* Vb = V + ((size_t)(b * GG + g) * SS) * HD;

    const int tid = threadIdx.x;
    const int lane = tid & 31;
    const int wid = tid >> 5;

    // load Q tile (64 x 128 fp16)
#pragma unroll
    for (int i = 0; i < 8; i++) {
        const int id = tid + i * 128;
        const int row = id >> 4, col = id & 15;
        CP_ASYNC16(sq + row * AT_ROWB + col * 16, Qb + row * HD + col * 8);
    }
    CP_COMMIT(); cp_wait<0>(); __syncthreads();

    // preload Q a-frags
    uint32_t aq[8][4];
    {
        const int row = wid * 16 + (lane & 15);
        const int c8 = (lane >> 4) * 8;
#pragma unroll
        for (int ks = 0; ks < 8; ks++)
            ldmatrix_x4(aq[ks], sq + row * AT_ROWB + (ks * 16 + c8) * 2);
    }

    float m_run[2] = {-1e30f, -1e30f};
    float l_run[2] = {0.0f, 0.0f};
    float o[16][4];
#pragma unroll
    for (int n = 0; n < 16; n++)
#pragma unroll
        for (int t = 0; t < 4; t++) o[n][t] = 0.0f;

    for (int kt = 0; kt <= qt; kt++) {
        __syncthreads();
#pragma unroll
        for (int i = 0; i < 8; i++) {
            const int id = tid + i * 128;
            const int row = id >> 4, col = id & 15;
            CP_ASYNC16(sk + row * AT_ROWB + col * 16,
                       Kb + (size_t)(kt * 64 + row) * HD + col * 8);
            CP_ASYNC16(sv + row * AT_ROWB + col * 16,
                       Vb + (size_t)(kt * 64 + row) * HD + col * 8);
        }
        CP_COMMIT(); cp_wait<0>(); __syncthreads();

        // ---- S = Q K^T ----
        float s[8][4];
#pragma unroll
        for (int j = 0; j < 8; j++)
#pragma unroll
            for (int t = 0; t < 4; t++) s[j][t] = 0.0f;

#pragma unroll
        for (int ks = 0; ks < 8; ks++) {
#pragma unroll
            for (int nb = 0; nb < 4; nb++) {
                uint32_t bv[4];
                const int row = nb * 16 + (lane & 15);
                const int col = ks * 16 + (lane >> 4) * 8;
                ldmatrix_x4(bv, sk + row * AT_ROWB + col * 2);
                uint32_t b0[2] = {bv[0], bv[2]};
                uint32_t b1[2] = {bv[1], bv[3]};
                mma_f16(s[nb * 2 + 0], aq[ks], b0);
                mma_f16(s[nb * 2 + 1], aq[ks], b1);
            }
        }

        // ---- online softmax ----
        if (kt == qt) {
            const int rbase = wid * 16 + (lane >> 2);
#pragma unroll
            for (int j = 0; j < 8; j++) {
#pragma unroll
                for (int t = 0; t < 4; t++) {
                    const int cc = j * 8 + (lane & 3) * 2 + (t & 1);
                    const int rr = rbase + (t >> 1) * 8;
                    if (cc > rr) s[j][t] = -1e30f;
                }
            }
        }
        float mx0 = -1e30f, mx1 = -1e30f;
#pragma unroll
        for (int j = 0; j < 8; j++) {
            mx0 = fmaxf(mx0, fmaxf(s[j][0], s[j][1]));
            mx1 = fmaxf(mx1, fmaxf(s[j][2], s[j][3]));
        }
        mx0 = fmaxf(mx0, __shfl_xor_sync(0xffffffffu, mx0, 1));
        mx0 = fmaxf(mx0, __shfl_xor_sync(0xffffffffu, mx0, 2));
        mx1 = fmaxf(mx1, __shfl_xor_sync(0xffffffffu, mx1, 1));
        mx1 = fmaxf(mx1, __shfl_xor_sync(0xffffffffu, mx1, 2));

        const float mn0 = fmaxf(m_run[0], mx0);
        const float mn1 = fmaxf(m_run[1], mx1);
        const float al0 = __expf(m_run[0] - mn0);
        const float al1 = __expf(m_run[1] - mn1);

        float sum0 = 0.0f, sum1 = 0.0f;
#pragma unroll
        for (int j = 0; j < 8; j++) {
            s[j][0] = __expf(s[j][0] - mn0);
            s[j][1] = __expf(s[j][1] - mn0);
            s[j][2] = __expf(s[j][2] - mn1);
            s[j][3] = __expf(s[j][3] - mn1);
            sum0 += s[j][0] + s[j][1];
            sum1 += s[j][2] + s[j][3];
        }
        sum0 += __shfl_xor_sync(0xffffffffu, sum0, 1);
        sum0 += __shfl_xor_sync(0xffffffffu, sum0, 2);
        sum1 += __shfl_xor_sync(0xffffffffu, sum1, 1);
        sum1 += __shfl_xor_sync(0xffffffffu, sum1, 2);

        l_run[0] = l_run[0] * al0 + sum0;
        l_run[1] = l_run[1] * al1 + sum1;
        m_run[0] = mn0;
        m_run[1] = mn1;

#pragma unroll
        for (int n = 0; n < 16; n++) {
            o[n][0] *= al0; o[n][1] *= al0;
            o[n][2] *= al1; o[n][3] *= al1;
        }

        // ---- O += P V ----
#pragma unroll
        for (int kk = 0; kk < 4; kk++) {
            uint32_t ap[4];
            ap[0] = pack_half2(s[2 * kk][0], s[2 * kk][1]);
            ap[1] = pack_half2(s[2 * kk][2], s[2 * kk][3]);
            ap[2] = pack_half2(s[2 * kk + 1][0], s[2 * kk + 1][1]);
            ap[3] = pack_half2(s[2 * kk + 1][2], s[2 * kk + 1][3]);
#pragma unroll
            for (int nb = 0; nb < 8; nb++) {
                uint32_t bv[4];
                const int row = kk * 16 + ((lane >> 3) & 1) * 8 + (lane & 7);
                const int col = nb * 16 + (lane >> 4) * 8;
                ldmatrix_x4t(bv, sv + row * AT_ROWB + col * 2);
                uint32_t b0[2] = {bv[0], bv[1]};
                uint32_t b1[2] = {bv[2], bv[3]};
                mma_f16(o[nb * 2 + 0], ap, b0);
                mma_f16(o[nb * 2 + 1], ap, b1);
            }
        }
    }

    // ---- write fp16 ctx ----
    const float inv0 = 1.0f / l_run[0];
    const float inv1 = 1.0f / l_run[1];
    const int r1 = qt * 64 + wid * 16 + (lane >> 2);
#pragma unroll
    for (int n = 0; n < 16; n++) {
        const int hd0 = n * 8 + (lane & 3) * 2;
        const size_t i1 = (size_t)(b * SS + r1) * HH + h * HD + hd0;
        const size_t i2 = (size_t)(b * SS + r1 + 8) * HH + h * HD + hd0;
        *(__half2*)(Ctx + i1) = __floats2half2_rn(o[n][0] * inv0, o[n][1] * inv0);
        *(__half2*)(Ctx + i2) = __floats2half2_rn(o[n][2] * inv1, o[n][3] * inv1);
    }
}

// =============================================================================
// Host launcher
// =============================================================================
extern "C" void kernel_launch(void* const* d_in, const int* in_sizes, int n_in,
                              void* d_out, int out_size)
{
    (void)in_sizes; (void)n_in; (void)out_size;
    const float* hidden  = (const float*)d_in[0];
    const float* rope    = (const float*)d_in[1];
    const float* w_qkv   = (const float*)d_in[2];
    const float* b_qkv   = (const float*)d_in[3];
    const float* w_dense = (const float*)d_in[4];
    float* out = (float*)d_out;

    float* qkv;
    __half *q, *k, *v, *ah, *wq, *wd, *ctx;
    cudaGetSymbolAddress((void**)&qkv, g_qkv);
    cudaGetSymbolAddress((void**)&q,   g_q);
    cudaGetSymbolAddress((void**)&k,   g_k);
    cudaGetSymbolAddress((void**)&v,   g_v);
    cudaGetSymbolAddress((void**)&ah,  g_ah);
    cudaGetSymbolAddress((void**)&wq,  g_wq);
    cudaGetSymbolAddress((void**)&wd,  g_wd);
    cudaGetSymbolAddress((void**)&ctx, g_ctx);

    cudaFuncSetAttribute(gemm_f16_kernel,
                         cudaFuncAttributeMaxDynamicSharedMemorySize, GEMM_SMEM);
    cudaFuncSetAttribute(attn_mma_kernel,
                         cudaFuncAttributeMaxDynamicSharedMemorySize, 3 * 64 * AT_ROWB);

    // 1) fp16 conversions
    {
        int n4 = MROWS * KDIM / 4;
        convert_f16_kernel<<<(n4 + 255) / 256, 256>>>(hidden, ah, n4);
    }
    {
        int n4 = KDIM * NQKV / 4;
        convert_f16_kernel<<<(n4 + 255) / 256, 256>>>(w_qkv, wq, n4);
    }
    {
        int n4 = KDIM * HH / 4;
        convert_f16_kernel<<<(n4 + 255) / 256, 256>>>(w_dense, wd, n4);
    }

    // 2) QKV GEMM + bias (fp16 single pass)
    gemm_f16_kernel<<<dim3(NQKV / GBN, MROWS / GBM), 256, GEMM_SMEM>>>(
        ah, wq, b_qkv, qkv, NQKV);

    // 3) RoPE + scatter to fp16 head-major
    {
        const int total = BB * SS * (NH + 2 * GG) * 64;
        rope_scatter_kernel<<<(total + 255) / 256, 256>>>(qkv, rope, q, k, v);
    }

    // 4) fp16 tensor-core flash attention (writes fp16 ctx)
    attn_mma_kernel<<<dim3(SS / 64, BB * NH), 128, 3 * 64 * AT_ROWB>>>(q, k, v, ctx);

    // 5) dense GEMM (fp16 single pass)
    gemm_f16_kernel<<<dim3(HH / GBN, MROWS / GBM), 256, GEMM_SMEM>>>(
        ctx, wd, nullptr, out, HH);
}